// round 2
// baseline (speedup 1.0000x reference)
#include <cuda_runtime.h>
#include <cuda_bf16.h>
#include <cstdint>
#include <cmath>

// ---------------------------------------------------------------------------
// Problem constants
// ---------------------------------------------------------------------------
#define Bb 4
#define Tt 4096
#define Dd 1024
#define Kk 64
#define Hh 4
#define KHh 16
#define Cc 64
#define MLPd 4096
#define Ntok (Bb * Tt)          // 16384 tokens
#define NCHUNK (Tt / Cc)        // 64 chunks per batch

// ---------------------------------------------------------------------------
// Scratch (static __device__ arrays; no allocation anywhere)
// ---------------------------------------------------------------------------
__device__ float g_xnorm[(size_t)Ntok * Dd];          // 64 MB
__device__ float g_beta [(size_t)Ntok * 2 * Kk];      //  8 MB (becomes intra in-place)
__device__ float g_c    [(size_t)Ntok * 2 * Kk];      //  8 MB (post-coupling)
__device__ float g_gate [(size_t)Ntok * Dd];          // 64 MB
__device__ float g_h    [(size_t)Ntok * Dd];          // 64 MB
__device__ float g_x1   [(size_t)Ntok * Dd];          // 64 MB
__device__ float g_x2n  [(size_t)Ntok * Dd];          // 64 MB
__device__ float g_hid  [(size_t)Ntok * MLPd];        // 256 MB

// ---------------------------------------------------------------------------
// LayerNorm (one block per row of 1024)
// ---------------------------------------------------------------------------
__global__ void __launch_bounds__(256) ln_kernel(
    const float* __restrict__ x, const float* __restrict__ gg,
    const float* __restrict__ bb, float* __restrict__ out)
{
    int row = blockIdx.x;
    int tid = threadIdx.x;
    const float4* xr = (const float4*)(x + (size_t)row * Dd);
    float4 v = xr[tid];
    float s  = v.x + v.y + v.z + v.w;
    float ss = v.x*v.x + v.y*v.y + v.z*v.z + v.w*v.w;
    #pragma unroll
    for (int o = 16; o; o >>= 1) {
        s  += __shfl_down_sync(0xffffffffu, s,  o);
        ss += __shfl_down_sync(0xffffffffu, ss, o);
    }
    __shared__ float sh_s[8], sh_ss[8];
    __shared__ float sh_m, sh_r;
    int w = tid >> 5, lane = tid & 31;
    if (!lane) { sh_s[w] = s; sh_ss[w] = ss; }
    __syncthreads();
    if (tid == 0) {
        float S = 0.f, SS = 0.f;
        #pragma unroll
        for (int i = 0; i < 8; ++i) { S += sh_s[i]; SS += sh_ss[i]; }
        float m = S * (1.0f / Dd);
        float var = SS * (1.0f / Dd) - m * m;
        sh_m = m;
        sh_r = rsqrtf(var + 1e-5f);
    }
    __syncthreads();
    float m = sh_m, r = sh_r;
    float4 g4 = ((const float4*)gg)[tid];
    float4 b4 = ((const float4*)bb)[tid];
    float4 o;
    o.x = (v.x - m) * r * g4.x + b4.x;
    o.y = (v.y - m) * r * g4.y + b4.y;
    o.z = (v.z - m) * r * g4.z + b4.z;
    o.w = (v.w - m) * r * g4.w + b4.w;
    ((float4*)(out + (size_t)row * Dd))[tid] = o;
}

// ---------------------------------------------------------------------------
// x1 = x + gate*h,  then LayerNorm(x1) -> x2n.  One block per row.
// ---------------------------------------------------------------------------
__global__ void __launch_bounds__(256) combine_ln2_kernel(
    const float* __restrict__ x, const float* __restrict__ gate,
    const float* __restrict__ h, const float* __restrict__ g2,
    const float* __restrict__ b2, float* __restrict__ x1,
    float* __restrict__ x2n)
{
    int row = blockIdx.x;
    int tid = threadIdx.x;
    size_t off = (size_t)row * 256 + tid;
    float4 xv = ((const float4*)x)[off];
    float4 gv = ((const float4*)gate)[off];
    float4 hv = ((const float4*)h)[off];
    float4 v;
    v.x = xv.x + gv.x * hv.x;
    v.y = xv.y + gv.y * hv.y;
    v.z = xv.z + gv.z * hv.z;
    v.w = xv.w + gv.w * hv.w;
    ((float4*)x1)[off] = v;

    float s  = v.x + v.y + v.z + v.w;
    float ss = v.x*v.x + v.y*v.y + v.z*v.z + v.w*v.w;
    #pragma unroll
    for (int o = 16; o; o >>= 1) {
        s  += __shfl_down_sync(0xffffffffu, s,  o);
        ss += __shfl_down_sync(0xffffffffu, ss, o);
    }
    __shared__ float sh_s[8], sh_ss[8];
    __shared__ float sh_m, sh_r;
    int w = tid >> 5, lane = tid & 31;
    if (!lane) { sh_s[w] = s; sh_ss[w] = ss; }
    __syncthreads();
    if (tid == 0) {
        float S = 0.f, SS = 0.f;
        #pragma unroll
        for (int i = 0; i < 8; ++i) { S += sh_s[i]; SS += sh_ss[i]; }
        float m = S * (1.0f / Dd);
        float var = SS * (1.0f / Dd) - m * m;
        sh_m = m;
        sh_r = rsqrtf(var + 1e-5f);
    }
    __syncthreads();
    float m = sh_m, r = sh_r;
    float4 g4 = ((const float4*)g2)[tid];
    float4 b4 = ((const float4*)b2)[tid];
    float4 o;
    o.x = (v.x - m) * r * g4.x + b4.x;
    o.y = (v.y - m) * r * g4.y + b4.y;
    o.z = (v.z - m) * r * g4.z + b4.z;
    o.w = (v.w - m) * r * g4.w + b4.w;
    ((float4*)x2n)[off] = o;
}

// ---------------------------------------------------------------------------
// Phase A: intra-chunk BACKWARD complex scan, in place on g_beta.
//   intra[63] = beta[63];  intra[j] = beta[j] + lambda * intra[j+1]
// (The reference's Toeplitz operator is upper-triangular:
//   intra[j] = sum_{s>=j} lambda^{s-j} beta[s].)
// Note position 63 keeps the RAW beta value, which is exactly the
// inter-chunk carry the reference injects at j=0 of the next chunk.
// One thread per (b, chunk, k): 16384 threads, 64 sequential steps each.
// ---------------------------------------------------------------------------
__global__ void __launch_bounds__(256) phaseA_kernel(
    float* __restrict__ beta, const float* __restrict__ ld,
    const float* __restrict__ fr)
{
    int tid = blockIdx.x * 256 + threadIdx.x;   // 0..16383
    int k = tid & 63;
    int chunk = (tid >> 6) & 63;
    int b = tid >> 12;
    float mag = 1.0f / (1.0f + expf(-ld[k]));
    float f = fr[k];
    float lr = mag * cosf(f), li = mag * sinf(f);
    size_t base = ((size_t)(b * Tt + chunk * Cc)) * 128 + k;
    float cr = 0.f, ci = 0.f;
    for (int j = Cc - 1; j >= 0; --j) {
        size_t idx = base + (size_t)j * 128;
        float br = beta[idx];
        float bi = beta[idx + 64];
        float nr = br + lr * cr - li * ci;
        float ni = bi + lr * ci + li * cr;
        cr = nr; ci = ni;
        beta[idx]      = cr;
        beta[idx + 64] = ci;
    }
}

// ---------------------------------------------------------------------------
// Phase C: out = intra + (chunk-start ? prev-token raw beta : 0),
// then 16x16 coupling per head.  One block (128 threads) per token.
// The carry term: out[n, j=0] += beta[n-1, 63]; since the backward scan
// leaves intra[n-1, 63] == beta[n-1, 63], that is just intra[tok-1].
// ---------------------------------------------------------------------------
__global__ void __launch_bounds__(128) phaseC_kernel(
    const float* __restrict__ intra, const float* __restrict__ coup,
    float* __restrict__ cout)
{
    int tg = blockIdx.x;                 // global token 0..16383
    int t = tg & (Tt - 1);
    int tid = threadIdx.x;               // 0..127

    __shared__ float cs[128];
    __shared__ float coups[Hh * KHh * KHh];   // 1024 floats
    #pragma unroll
    for (int i = tid; i < Hh * KHh * KHh; i += 128) coups[i] = coup[i];

    if (tid < 64) {
        int k = tid;
        size_t ib = (size_t)tg * 128 + k;
        float ir = intra[ib];
        float ii = intra[ib + 64];
        if (((t & (Cc - 1)) == 0) && (t > 0)) {
            // chunk start (not first chunk of the batch): add carry
            size_t pb = (size_t)(tg - 1) * 128 + k;
            ir += intra[pb];
            ii += intra[pb + 64];
        }
        cs[k]      = ir;
        cs[64 + k] = ii;
    }
    __syncthreads();

    int m = tid;
    int part = m >> 6;        // 0 = real, 1 = imag
    int mm = m & 63;
    int hh = mm >> 4, j = mm & 15;
    const float* cp = &coups[(hh * KHh + j) * KHh];
    const float* cv = &cs[part * 64 + hh * KHh];
    float acc = 0.f;
    #pragma unroll
    for (int k = 0; k < KHh; ++k) acc += cp[k] * cv[k];
    cout[(size_t)tg * 128 + m] = acc;
}

// ---------------------------------------------------------------------------
// Tiled fp32 SGEMM: C(MxN) = A(MxKd, row-major) * W(NxKd, row-major)^T
// 128x128 tile, BK=16, 256 threads, 8x8 per-thread microtile.
// M, N multiple of 128; Kd multiple of 16 (all shapes here satisfy this).
// EPI: 0 = none, 1 = sigmoid(acc+bias), 2 = silu(acc+bias),
//      3 = acc + bias + res
// ---------------------------------------------------------------------------
template <int EPI>
__global__ void __launch_bounds__(256) sgemm_kernel(
    const float* __restrict__ A, const float* __restrict__ W,
    const float* __restrict__ bias, const float* __restrict__ res,
    float* __restrict__ Cout, int M, int N, int Kd)
{
    const int BM = 128, BN = 128, BK = 16;
    __shared__ float As[BK][132];
    __shared__ float Bs[BK][132];

    int tid = threadIdx.x;
    int tx = tid & 15;   // n direction
    int ty = tid >> 4;   // m direction
    int m0 = blockIdx.y * BM;
    int n0 = blockIdx.x * BN;

    const float* Aptr = A + (size_t)m0 * Kd;
    const float* Wptr = W + (size_t)n0 * Kd;

    float acc[8][8];
    #pragma unroll
    for (int i = 0; i < 8; ++i)
        #pragma unroll
        for (int j = 0; j < 8; ++j) acc[i][j] = 0.f;

    for (int k0 = 0; k0 < Kd; k0 += BK) {
        #pragma unroll
        for (int it = 0; it < 2; ++it) {
            int l = tid + 256 * it;        // 0..511
            int row = l >> 2;
            int kq = (l & 3) * 4;
            float4 av = *(const float4*)(Aptr + (size_t)row * Kd + k0 + kq);
            As[kq + 0][row] = av.x; As[kq + 1][row] = av.y;
            As[kq + 2][row] = av.z; As[kq + 3][row] = av.w;
            float4 bv = *(const float4*)(Wptr + (size_t)row * Kd + k0 + kq);
            Bs[kq + 0][row] = bv.x; Bs[kq + 1][row] = bv.y;
            Bs[kq + 2][row] = bv.z; Bs[kq + 3][row] = bv.w;
        }
        __syncthreads();
        #pragma unroll
        for (int kk = 0; kk < BK; ++kk) {
            float a[8], bvv[8];
            *(float4*)&a[0]   = *(const float4*)&As[kk][ty * 8];
            *(float4*)&a[4]   = *(const float4*)&As[kk][ty * 8 + 4];
            *(float4*)&bvv[0] = *(const float4*)&Bs[kk][tx * 8];
            *(float4*)&bvv[4] = *(const float4*)&Bs[kk][tx * 8 + 4];
            #pragma unroll
            for (int i = 0; i < 8; ++i)
                #pragma unroll
                for (int j = 0; j < 8; ++j)
                    acc[i][j] = fmaf(a[i], bvv[j], acc[i][j]);
        }
        __syncthreads();
    }

    float bs[8];
    #pragma unroll
    for (int j = 0; j < 8; ++j)
        bs[j] = (EPI == 0) ? 0.f : bias[n0 + tx * 8 + j];

    #pragma unroll
    for (int i = 0; i < 8; ++i) {
        int row = m0 + ty * 8 + i;
        size_t base = (size_t)row * N + n0 + tx * 8;
        float v[8];
        #pragma unroll
        for (int j = 0; j < 8; ++j) {
            float z = acc[i][j];
            if (EPI == 1) {                 // sigmoid(z + b)
                z += bs[j];
                z = 1.0f / (1.0f + expf(-z));
            } else if (EPI == 2) {          // silu(z + b)
                z += bs[j];
                z = z / (1.0f + expf(-z));
            } else if (EPI == 3) {          // z + b + res
                z += bs[j] + res[base + j];
            }
            v[j] = z;
        }
        *(float4*)&Cout[base]     = *(float4*)&v[0];
        *(float4*)&Cout[base + 4] = *(float4*)&v[4];
    }
}

// ---------------------------------------------------------------------------
// Launch
// ---------------------------------------------------------------------------
extern "C" void kernel_launch(void* const* d_in, const int* in_sizes, int n_in,
                              void* d_out, int out_size)
{
    const float* x         = (const float*)d_in[0];
    const float* w_in      = (const float*)d_in[1];
    const float* w_out     = (const float*)d_in[2];
    const float* w_gate    = (const float*)d_in[3];
    const float* b_gate    = (const float*)d_in[4];
    const float* log_decay = (const float*)d_in[5];
    const float* frequency = (const float*)d_in[6];
    const float* coupling  = (const float*)d_in[7];
    const float* w_mlp1    = (const float*)d_in[8];
    const float* b_mlp1    = (const float*)d_in[9];
    const float* w_mlp2    = (const float*)d_in[10];
    const float* b_mlp2    = (const float*)d_in[11];
    const float* ln1_g     = (const float*)d_in[12];
    const float* ln1_b     = (const float*)d_in[13];
    const float* ln2_g     = (const float*)d_in[14];
    const float* ln2_b     = (const float*)d_in[15];
    float* out = (float*)d_out;

    float *xnorm, *beta, *cbuf, *gate, *hbuf, *x1, *x2n, *hid;
    cudaGetSymbolAddress((void**)&xnorm, g_xnorm);
    cudaGetSymbolAddress((void**)&beta,  g_beta);
    cudaGetSymbolAddress((void**)&cbuf,  g_c);
    cudaGetSymbolAddress((void**)&gate,  g_gate);
    cudaGetSymbolAddress((void**)&hbuf,  g_h);
    cudaGetSymbolAddress((void**)&x1,    g_x1);
    cudaGetSymbolAddress((void**)&x2n,   g_x2n);
    cudaGetSymbolAddress((void**)&hid,   g_hid);

    // 1. LN1
    ln_kernel<<<Ntok, 256>>>(x, ln1_g, ln1_b, xnorm);
    // 2. beta = xnorm @ w_in^T   (16384 x 128 x 1024)
    sgemm_kernel<0><<<dim3(1, Ntok / 128), 256>>>(xnorm, w_in, nullptr, nullptr,
                                                  beta, Ntok, 128, Dd);
    // 3. intra-chunk backward scan (in place)
    phaseA_kernel<<<64, 256>>>(beta, log_decay, frequency);
    // 4. carry apply + coupling
    phaseC_kernel<<<Ntok, 128>>>(beta, coupling, cbuf);
    // 5. gate = sigmoid(xnorm @ w_gate^T + b_gate)   (16384 x 1024 x 1024)
    sgemm_kernel<1><<<dim3(Dd / 128, Ntok / 128), 256>>>(xnorm, w_gate, b_gate,
                                                         nullptr, gate, Ntok, Dd, Dd);
    // 6. h = cbuf @ w_out^T   (16384 x 1024 x 128)
    sgemm_kernel<0><<<dim3(Dd / 128, Ntok / 128), 256>>>(cbuf, w_out, nullptr,
                                                         nullptr, hbuf, Ntok, Dd, 128);
    // 7. x1 = x + gate*h ; x2n = LN2(x1)
    combine_ln2_kernel<<<Ntok, 256>>>(x, gate, hbuf, ln2_g, ln2_b, x1, x2n);
    // 8. hid = silu(x2n @ w_mlp1^T + b1)   (16384 x 4096 x 1024)
    sgemm_kernel<2><<<dim3(MLPd / 128, Ntok / 128), 256>>>(x2n, w_mlp1, b_mlp1,
                                                           nullptr, hid, Ntok, MLPd, Dd);
    // 9. out = hid @ w_mlp2^T + b2 + x1   (16384 x 1024 x 4096)
    sgemm_kernel<3><<<dim3(Dd / 128, Ntok / 128), 256>>>(hid, w_mlp2, b_mlp2,
                                                         x1, out, Ntok, Dd, MLPd);
    (void)in_sizes; (void)n_in; (void)out_size;
}

// round 6
// speedup vs baseline: 2.0548x; 2.0548x over previous
#include <cuda_runtime.h>
#include <cuda_bf16.h>
#include <cstdint>
#include <cmath>

// ---------------------------------------------------------------------------
// Problem constants
// ---------------------------------------------------------------------------
#define Bb 4
#define Tt 4096
#define Dd 1024
#define Kk 64
#define Hh 4
#define KHh 16
#define Cc 64
#define MLPd 4096
#define Ntok (Bb * Tt)          // 16384 tokens
#define NCHUNK (Tt / Cc)        // 64 chunks per batch

// ---------------------------------------------------------------------------
// Scratch (static __device__ arrays; no allocation anywhere)
// ---------------------------------------------------------------------------
__device__ float g_xnorm[(size_t)Ntok * Dd];
__device__ float g_beta [(size_t)Ntok * 2 * Kk];
__device__ float g_c    [(size_t)Ntok * 2 * Kk];
__device__ float g_gate [(size_t)Ntok * Dd];
__device__ float g_h    [(size_t)Ntok * Dd];
__device__ float g_x1   [(size_t)Ntok * Dd];
__device__ float g_x2n  [(size_t)Ntok * Dd];
__device__ float g_hid  [(size_t)Ntok * MLPd];

// ---------------------------------------------------------------------------
// LayerNorm (one block per row of 1024)
// ---------------------------------------------------------------------------
__global__ void __launch_bounds__(256) ln_kernel(
    const float* __restrict__ x, const float* __restrict__ gg,
    const float* __restrict__ bb, float* __restrict__ out)
{
    int row = blockIdx.x;
    int tid = threadIdx.x;
    const float4* xr = (const float4*)(x + (size_t)row * Dd);
    float4 v = xr[tid];
    float s  = v.x + v.y + v.z + v.w;
    float ss = v.x*v.x + v.y*v.y + v.z*v.z + v.w*v.w;
    #pragma unroll
    for (int o = 16; o; o >>= 1) {
        s  += __shfl_down_sync(0xffffffffu, s,  o);
        ss += __shfl_down_sync(0xffffffffu, ss, o);
    }
    __shared__ float sh_s[8], sh_ss[8];
    __shared__ float sh_m, sh_r;
    int w = tid >> 5, lane = tid & 31;
    if (!lane) { sh_s[w] = s; sh_ss[w] = ss; }
    __syncthreads();
    if (tid == 0) {
        float S = 0.f, SS = 0.f;
        #pragma unroll
        for (int i = 0; i < 8; ++i) { S += sh_s[i]; SS += sh_ss[i]; }
        float m = S * (1.0f / Dd);
        float var = SS * (1.0f / Dd) - m * m;
        sh_m = m;
        sh_r = rsqrtf(var + 1e-5f);
    }
    __syncthreads();
    float m = sh_m, r = sh_r;
    float4 g4 = ((const float4*)gg)[tid];
    float4 b4 = ((const float4*)bb)[tid];
    float4 o;
    o.x = (v.x - m) * r * g4.x + b4.x;
    o.y = (v.y - m) * r * g4.y + b4.y;
    o.z = (v.z - m) * r * g4.z + b4.z;
    o.w = (v.w - m) * r * g4.w + b4.w;
    ((float4*)(out + (size_t)row * Dd))[tid] = o;
}

// ---------------------------------------------------------------------------
// x1 = x + gate*h,  then LayerNorm(x1) -> x2n.  One block per row.
// ---------------------------------------------------------------------------
__global__ void __launch_bounds__(256) combine_ln2_kernel(
    const float* __restrict__ x, const float* __restrict__ gate,
    const float* __restrict__ h, const float* __restrict__ g2,
    const float* __restrict__ b2, float* __restrict__ x1,
    float* __restrict__ x2n)
{
    int row = blockIdx.x;
    int tid = threadIdx.x;
    size_t off = (size_t)row * 256 + tid;
    float4 xv = ((const float4*)x)[off];
    float4 gv = ((const float4*)gate)[off];
    float4 hv = ((const float4*)h)[off];
    float4 v;
    v.x = xv.x + gv.x * hv.x;
    v.y = xv.y + gv.y * hv.y;
    v.z = xv.z + gv.z * hv.z;
    v.w = xv.w + gv.w * hv.w;
    ((float4*)x1)[off] = v;

    float s  = v.x + v.y + v.z + v.w;
    float ss = v.x*v.x + v.y*v.y + v.z*v.z + v.w*v.w;
    #pragma unroll
    for (int o = 16; o; o >>= 1) {
        s  += __shfl_down_sync(0xffffffffu, s,  o);
        ss += __shfl_down_sync(0xffffffffu, ss, o);
    }
    __shared__ float sh_s[8], sh_ss[8];
    __shared__ float sh_m, sh_r;
    int w = tid >> 5, lane = tid & 31;
    if (!lane) { sh_s[w] = s; sh_ss[w] = ss; }
    __syncthreads();
    if (tid == 0) {
        float S = 0.f, SS = 0.f;
        #pragma unroll
        for (int i = 0; i < 8; ++i) { S += sh_s[i]; SS += sh_ss[i]; }
        float m = S * (1.0f / Dd);
        float var = SS * (1.0f / Dd) - m * m;
        sh_m = m;
        sh_r = rsqrtf(var + 1e-5f);
    }
    __syncthreads();
    float m = sh_m, r = sh_r;
    float4 g4 = ((const float4*)g2)[tid];
    float4 b4 = ((const float4*)b2)[tid];
    float4 o;
    o.x = (v.x - m) * r * g4.x + b4.x;
    o.y = (v.y - m) * r * g4.y + b4.y;
    o.z = (v.z - m) * r * g4.z + b4.z;
    o.w = (v.w - m) * r * g4.w + b4.w;
    ((float4*)x2n)[off] = o;
}

// ---------------------------------------------------------------------------
// Phase A: intra-chunk BACKWARD complex scan, in place on g_beta.
// ---------------------------------------------------------------------------
__global__ void __launch_bounds__(256) phaseA_kernel(
    float* __restrict__ beta, const float* __restrict__ ld,
    const float* __restrict__ fr)
{
    int tid = blockIdx.x * 256 + threadIdx.x;   // 0..16383
    int k = tid & 63;
    int chunk = (tid >> 6) & 63;
    int b = tid >> 12;
    float mag = 1.0f / (1.0f + expf(-ld[k]));
    float f = fr[k];
    float lr = mag * cosf(f), li = mag * sinf(f);
    size_t base = ((size_t)(b * Tt + chunk * Cc)) * 128 + k;
    float cr = 0.f, ci = 0.f;
    for (int j = Cc - 1; j >= 0; --j) {
        size_t idx = base + (size_t)j * 128;
        float br = beta[idx];
        float bi = beta[idx + 64];
        float nr = br + lr * cr - li * ci;
        float ni = bi + lr * ci + li * cr;
        cr = nr; ci = ni;
        beta[idx]      = cr;
        beta[idx + 64] = ci;
    }
}

// ---------------------------------------------------------------------------
// Phase C: carry + 16x16 coupling.  One block (128 threads) per token.
// ---------------------------------------------------------------------------
__global__ void __launch_bounds__(128) phaseC_kernel(
    const float* __restrict__ intra, const float* __restrict__ coup,
    float* __restrict__ cout)
{
    int tg = blockIdx.x;                 // global token
    int t = tg & (Tt - 1);
    int tid = threadIdx.x;

    __shared__ float cs[128];
    __shared__ float coups[Hh * KHh * KHh];
    #pragma unroll
    for (int i = tid; i < Hh * KHh * KHh; i += 128) coups[i] = coup[i];

    if (tid < 64) {
        int k = tid;
        size_t ib = (size_t)tg * 128 + k;
        float ir = intra[ib];
        float ii = intra[ib + 64];
        if (((t & (Cc - 1)) == 0) && (t > 0)) {
            size_t pb = (size_t)(tg - 1) * 128 + k;
            ir += intra[pb];
            ii += intra[pb + 64];
        }
        cs[k]      = ir;
        cs[64 + k] = ii;
    }
    __syncthreads();

    int m = tid;
    int part = m >> 6;
    int mm = m & 63;
    int hh = mm >> 4, j = mm & 15;
    const float* cp = &coups[(hh * KHh + j) * KHh];
    const float* cv = &cs[part * 64 + hh * KHh];
    float acc = 0.f;
    #pragma unroll
    for (int k = 0; k < KHh; ++k) acc += cp[k] * cv[k];
    cout[(size_t)tg * 128 + m] = acc;
}

// ---------------------------------------------------------------------------
// Tensor-core GEMM with bf16 split-precision (hi/lo), fp32 accumulate.
//   C(MxN) = A(MxKd, row-major) * W(NxKd, row-major)^T
// Tile 128x128x32, 256 threads (8 warps: 4(m) x 2(n)), warp tile 32x64.
// Each fp32 element is split a = hi(bf16) + lo(bf16); 3 MMAs per product
// (hi*hi + hi*lo + lo*hi) recover ~17 mantissa bits (rel err ~1e-5).
// B operand: W rows are n, cols are k (k contiguous) == K x N col-major,
// exactly what mma row.col wants -> NON-trans ldmatrix (the .trans variant
// was the Round-5 bug: it delivered consecutive-n pairs instead of
// consecutive-k pairs per register).
// EPI: 0 none, 1 sigmoid(z+b), 2 silu(z+b), 3 z+b+res
// ---------------------------------------------------------------------------
__device__ __forceinline__ void ldsm_x4(uint32_t* r, uint32_t addr) {
    asm volatile("ldmatrix.sync.aligned.m8n8.x4.shared.b16 {%0,%1,%2,%3}, [%4];"
                 : "=r"(r[0]), "=r"(r[1]), "=r"(r[2]), "=r"(r[3]) : "r"(addr));
}
__device__ __forceinline__ void mma_bf16(float* d, const uint32_t* a, const uint32_t* b) {
    asm volatile(
        "mma.sync.aligned.m16n8k16.row.col.f32.bf16.bf16.f32 "
        "{%0,%1,%2,%3}, {%4,%5,%6,%7}, {%8,%9}, {%0,%1,%2,%3};"
        : "+f"(d[0]), "+f"(d[1]), "+f"(d[2]), "+f"(d[3])
        : "r"(a[0]), "r"(a[1]), "r"(a[2]), "r"(a[3]), "r"(b[0]), "r"(b[1]));
}

#define LDP 40   // padded bf16 row stride (conflict-free for ldmatrix)

template <int EPI>
__global__ void __launch_bounds__(256) mma_gemm_kernel(
    const float* __restrict__ A, const float* __restrict__ W,
    const float* __restrict__ bias, const float* __restrict__ res,
    float* __restrict__ Cout, int M, int N, int Kd)
{
    __shared__ __nv_bfloat16 As_hi[128][LDP];
    __shared__ __nv_bfloat16 As_lo[128][LDP];
    __shared__ __nv_bfloat16 Bs_hi[128][LDP];
    __shared__ __nv_bfloat16 Bs_lo[128][LDP];

    int t = threadIdx.x;
    int lane = t & 31, w = t >> 5;
    int wm = (w & 3) * 32;     // warp m offset in tile
    int wn = (w >> 2) * 64;    // warp n offset in tile
    int m0 = blockIdx.y * 128;
    int n0 = blockIdx.x * 128;

    // global load coordinates: thread covers one 128-row, 16-col half
    int lrow = t >> 1;
    int lk   = (t & 1) * 16;
    const float* Abase = A + (size_t)(m0 + lrow) * Kd + lk;
    const float* Wbase = W + (size_t)(n0 + lrow) * Kd + lk;

    float acc[2][8][4];
    #pragma unroll
    for (int i = 0; i < 2; ++i)
        #pragma unroll
        for (int j = 0; j < 8; ++j)
            #pragma unroll
            for (int e = 0; e < 4; ++e) acc[i][j][e] = 0.f;

    // ldmatrix lane->address patterns
    // A (x4): lanes 0-15 -> rows (m), lanes 16-31 -> k+8 column half
    int a_row = wm + (lane & 15);
    int a_coladd = (lane >> 4) << 3;
    // B (x4, non-trans): lanes 0-7 n-low/k-low, 8-15 n-low/k-high,
    //                    16-23 n-high/k-low, 24-31 n-high/k-high
    int b_row = wn + (lane & 7) + ((lane >> 4) << 3);
    int b_coladd = ((lane >> 3) & 1) << 3;

    uint32_t sAhi = (uint32_t)__cvta_generic_to_shared(&As_hi[0][0]);
    uint32_t sAlo = (uint32_t)__cvta_generic_to_shared(&As_lo[0][0]);
    uint32_t sBhi = (uint32_t)__cvta_generic_to_shared(&Bs_hi[0][0]);
    uint32_t sBlo = (uint32_t)__cvta_generic_to_shared(&Bs_lo[0][0]);

    float4 ra[4], rb[4];
    // preload k-tile 0
    #pragma unroll
    for (int q = 0; q < 4; ++q) {
        ra[q] = *(const float4*)(Abase + q * 4);
        rb[q] = *(const float4*)(Wbase + q * 4);
    }

    int nk = Kd >> 5;
    for (int kt = 0; kt < nk; ++kt) {
        // split + store current tile registers to smem
        #pragma unroll
        for (int q = 0; q < 4; ++q) {
            float ev[4] = {ra[q].x, ra[q].y, ra[q].z, ra[q].w};
            __nv_bfloat162 h01, h23, l01, l23;
            h01.x = __float2bfloat16_rn(ev[0]);
            h01.y = __float2bfloat16_rn(ev[1]);
            h23.x = __float2bfloat16_rn(ev[2]);
            h23.y = __float2bfloat16_rn(ev[3]);
            l01.x = __float2bfloat16_rn(ev[0] - __bfloat162float(h01.x));
            l01.y = __float2bfloat16_rn(ev[1] - __bfloat162float(h01.y));
            l23.x = __float2bfloat16_rn(ev[2] - __bfloat162float(h23.x));
            l23.y = __float2bfloat16_rn(ev[3] - __bfloat162float(h23.y));
            *(__nv_bfloat162*)&As_hi[lrow][lk + q * 4]     = h01;
            *(__nv_bfloat162*)&As_hi[lrow][lk + q * 4 + 2] = h23;
            *(__nv_bfloat162*)&As_lo[lrow][lk + q * 4]     = l01;
            *(__nv_bfloat162*)&As_lo[lrow][lk + q * 4 + 2] = l23;

            float fv[4] = {rb[q].x, rb[q].y, rb[q].z, rb[q].w};
            __nv_bfloat162 g01, g23, m01, m23;
            g01.x = __float2bfloat16_rn(fv[0]);
            g01.y = __float2bfloat16_rn(fv[1]);
            g23.x = __float2bfloat16_rn(fv[2]);
            g23.y = __float2bfloat16_rn(fv[3]);
            m01.x = __float2bfloat16_rn(fv[0] - __bfloat162float(g01.x));
            m01.y = __float2bfloat16_rn(fv[1] - __bfloat162float(g01.y));
            m23.x = __float2bfloat16_rn(fv[2] - __bfloat162float(g23.x));
            m23.y = __float2bfloat16_rn(fv[3] - __bfloat162float(g23.y));
            *(__nv_bfloat162*)&Bs_hi[lrow][lk + q * 4]     = g01;
            *(__nv_bfloat162*)&Bs_hi[lrow][lk + q * 4 + 2] = g23;
            *(__nv_bfloat162*)&Bs_lo[lrow][lk + q * 4]     = m01;
            *(__nv_bfloat162*)&Bs_lo[lrow][lk + q * 4 + 2] = m23;
        }
        __syncthreads();

        // prefetch next tile into registers while we compute
        if (kt + 1 < nk) {
            const float* An = Abase + (kt + 1) * 32;
            const float* Wn = Wbase + (kt + 1) * 32;
            #pragma unroll
            for (int q = 0; q < 4; ++q) {
                ra[q] = *(const float4*)(An + q * 4);
                rb[q] = *(const float4*)(Wn + q * 4);
            }
        }

        #pragma unroll
        for (int kk = 0; kk < 32; kk += 16) {
            uint32_t Ah[2][4], Al[2][4], Bh[4][4], Bl[4][4];
            #pragma unroll
            for (int im = 0; im < 2; ++im) {
                uint32_t off = (uint32_t)((a_row + im * 16) * LDP + kk + a_coladd) * 2;
                ldsm_x4(Ah[im], sAhi + off);
                ldsm_x4(Al[im], sAlo + off);
            }
            #pragma unroll
            for (int q = 0; q < 4; ++q) {
                uint32_t off = (uint32_t)((b_row + q * 16) * LDP + kk + b_coladd) * 2;
                ldsm_x4(Bh[q], sBhi + off);   // NON-trans (fixed)
                ldsm_x4(Bl[q], sBlo + off);   // NON-trans (fixed)
            }
            #pragma unroll
            for (int im = 0; im < 2; ++im)
                #pragma unroll
                for (int q = 0; q < 4; ++q)
                    #pragma unroll
                    for (int hf = 0; hf < 2; ++hf) {
                        float* d = acc[im][q * 2 + hf];
                        mma_bf16(d, Ah[im], &Bh[q][hf * 2]);
                        mma_bf16(d, Ah[im], &Bl[q][hf * 2]);
                        mma_bf16(d, Al[im], &Bh[q][hf * 2]);
                    }
        }
        __syncthreads();
    }

    // epilogue: d-frag layout row = base + (lane>>2) (+8), col = base + (lane&3)*2
    #pragma unroll
    for (int im = 0; im < 2; ++im) {
        int r0 = m0 + wm + im * 16 + (lane >> 2);
        #pragma unroll
        for (int jn = 0; jn < 8; ++jn) {
            int c0 = n0 + wn + jn * 8 + (lane & 3) * 2;
            float b0 = 0.f, b1 = 0.f;
            if (EPI != 0) { b0 = bias[c0]; b1 = bias[c0 + 1]; }
            float z[4] = {acc[im][jn][0], acc[im][jn][1],
                          acc[im][jn][2], acc[im][jn][3]};
            #pragma unroll
            for (int e = 0; e < 4; ++e) {
                float bb = (e & 1) ? b1 : b0;
                float v = z[e];
                if (EPI == 1) { v += bb; v = 1.0f / (1.0f + expf(-v)); }
                else if (EPI == 2) { v += bb; v = v / (1.0f + expf(-v)); }
                z[e] = v;
            }
            size_t o0 = (size_t)r0 * N + c0;
            size_t o1 = (size_t)(r0 + 8) * N + c0;
            if (EPI == 3) {
                z[0] += b0 + res[o0]; z[1] += b1 + res[o0 + 1];
                z[2] += b0 + res[o1]; z[3] += b1 + res[o1 + 1];
            }
            *(float2*)&Cout[o0] = make_float2(z[0], z[1]);
            *(float2*)&Cout[o1] = make_float2(z[2], z[3]);
        }
    }
}

// ---------------------------------------------------------------------------
// Launch
// ---------------------------------------------------------------------------
extern "C" void kernel_launch(void* const* d_in, const int* in_sizes, int n_in,
                              void* d_out, int out_size)
{
    const float* x         = (const float*)d_in[0];
    const float* w_in      = (const float*)d_in[1];
    const float* w_out     = (const float*)d_in[2];
    const float* w_gate    = (const float*)d_in[3];
    const float* b_gate    = (const float*)d_in[4];
    const float* log_decay = (const float*)d_in[5];
    const float* frequency = (const float*)d_in[6];
    const float* coupling  = (const float*)d_in[7];
    const float* w_mlp1    = (const float*)d_in[8];
    const float* b_mlp1    = (const float*)d_in[9];
    const float* w_mlp2    = (const float*)d_in[10];
    const float* b_mlp2    = (const float*)d_in[11];
    const float* ln1_g     = (const float*)d_in[12];
    const float* ln1_b     = (const float*)d_in[13];
    const float* ln2_g     = (const float*)d_in[14];
    const float* ln2_b     = (const float*)d_in[15];
    float* out = (float*)d_out;

    float *xnorm, *beta, *cbuf, *gate, *hbuf, *x1, *x2n, *hid;
    cudaGetSymbolAddress((void**)&xnorm, g_xnorm);
    cudaGetSymbolAddress((void**)&beta,  g_beta);
    cudaGetSymbolAddress((void**)&cbuf,  g_c);
    cudaGetSymbolAddress((void**)&gate,  g_gate);
    cudaGetSymbolAddress((void**)&hbuf,  g_h);
    cudaGetSymbolAddress((void**)&x1,    g_x1);
    cudaGetSymbolAddress((void**)&x2n,   g_x2n);
    cudaGetSymbolAddress((void**)&hid,   g_hid);

    // 1. LN1
    ln_kernel<<<Ntok, 256>>>(x, ln1_g, ln1_b, xnorm);
    // 2. beta = xnorm @ w_in^T   (16384 x 128 x 1024)
    mma_gemm_kernel<0><<<dim3(1, Ntok / 128), 256>>>(xnorm, w_in, nullptr, nullptr,
                                                     beta, Ntok, 128, Dd);
    // 3. intra-chunk backward scan (in place)
    phaseA_kernel<<<64, 256>>>(beta, log_decay, frequency);
    // 4. carry apply + coupling
    phaseC_kernel<<<Ntok, 128>>>(beta, coupling, cbuf);
    // 5. gate = sigmoid(xnorm @ w_gate^T + b_gate)   (16384 x 1024 x 1024)
    mma_gemm_kernel<1><<<dim3(Dd / 128, Ntok / 128), 256>>>(xnorm, w_gate, b_gate,
                                                            nullptr, gate, Ntok, Dd, Dd);
    // 6. h = cbuf @ w_out^T   (16384 x 1024 x 128)
    mma_gemm_kernel<0><<<dim3(Dd / 128, Ntok / 128), 256>>>(cbuf, w_out, nullptr,
                                                            nullptr, hbuf, Ntok, Dd, 128);
    // 7. x1 = x + gate*h ; x2n = LN2(x1)
    combine_ln2_kernel<<<Ntok, 256>>>(x, gate, hbuf, ln2_g, ln2_b, x1, x2n);
    // 8. hid = silu(x2n @ w_mlp1^T + b1)   (16384 x 4096 x 1024)
    mma_gemm_kernel<2><<<dim3(MLPd / 128, Ntok / 128), 256>>>(x2n, w_mlp1, b_mlp1,
                                                              nullptr, hid, Ntok, MLPd, Dd);
    // 9. out = hid @ w_mlp2^T + b2 + x1   (16384 x 1024 x 4096)
    mma_gemm_kernel<3><<<dim3(Dd / 128, Ntok / 128), 256>>>(hid, w_mlp2, b_mlp2,
                                                            x1, out, Ntok, Dd, MLPd);
    (void)in_sizes; (void)n_in; (void)out_size;
}

// round 9
// speedup vs baseline: 2.8947x; 1.4087x over previous
#include <cuda_runtime.h>
#include <cuda_bf16.h>
#include <cstdint>
#include <cmath>

// ---------------------------------------------------------------------------
// Problem constants
// ---------------------------------------------------------------------------
#define Bb 4
#define Tt 4096
#define Dd 1024
#define Kk 64
#define Hh 4
#define KHh 16
#define Cc 64
#define MLPd 4096
#define Ntok (Bb * Tt)          // 16384 tokens

// ---------------------------------------------------------------------------
// Scratch (static __device__ arrays; no allocation anywhere)
// ---------------------------------------------------------------------------
__device__ __nv_bfloat16 g_xn_hi [(size_t)Ntok * Dd];
__device__ __nv_bfloat16 g_xn_lo [(size_t)Ntok * Dd];
__device__ float         g_beta  [(size_t)Ntok * 2 * Kk];
__device__ __nv_bfloat16 g_c_hi  [(size_t)Ntok * 2 * Kk];
__device__ __nv_bfloat16 g_c_lo  [(size_t)Ntok * 2 * Kk];
__device__ float         g_gate  [(size_t)Ntok * Dd];
__device__ float         g_h     [(size_t)Ntok * Dd];
__device__ float         g_x1    [(size_t)Ntok * Dd];
__device__ __nv_bfloat16 g_x2_hi [(size_t)Ntok * Dd];
__device__ __nv_bfloat16 g_x2_lo [(size_t)Ntok * Dd];
__device__ __nv_bfloat16 g_hid_hi[(size_t)Ntok * MLPd];
__device__ __nv_bfloat16 g_hid_lo[(size_t)Ntok * MLPd];
// split weights
__device__ __nv_bfloat16 g_win_hi [2 * Kk * Dd];
__device__ __nv_bfloat16 g_win_lo [2 * Kk * Dd];
__device__ __nv_bfloat16 g_wgt_hi [Dd * Dd];
__device__ __nv_bfloat16 g_wgt_lo [Dd * Dd];
__device__ __nv_bfloat16 g_wout_hi[Dd * 2 * Kk];
__device__ __nv_bfloat16 g_wout_lo[Dd * 2 * Kk];
__device__ __nv_bfloat16 g_wm1_hi [(size_t)MLPd * Dd];
__device__ __nv_bfloat16 g_wm1_lo [(size_t)MLPd * Dd];
__device__ __nv_bfloat16 g_wm2_hi [(size_t)Dd * MLPd];
__device__ __nv_bfloat16 g_wm2_lo [(size_t)Dd * MLPd];

// ---------------------------------------------------------------------------
// helpers
// ---------------------------------------------------------------------------
__device__ __forceinline__ void split2(float a, float b,
                                       __nv_bfloat162& h, __nv_bfloat162& l) {
    h.x = __float2bfloat16_rn(a);
    h.y = __float2bfloat16_rn(b);
    l.x = __float2bfloat16_rn(a - __bfloat162float(h.x));
    l.y = __float2bfloat16_rn(b - __bfloat162float(h.y));
}

// ---------------------------------------------------------------------------
// Weight split: fp32 -> (hi, lo) bf16, elementwise (vector of 4)
// ---------------------------------------------------------------------------
__global__ void __launch_bounds__(256) split_kernel(
    const float* __restrict__ in, __nv_bfloat16* __restrict__ hi,
    __nv_bfloat16* __restrict__ lo, int n4)
{
    int i = blockIdx.x * 256 + threadIdx.x;
    if (i >= n4) return;
    float4 v = ((const float4*)in)[i];
    __nv_bfloat162 h01, l01, h23, l23;
    split2(v.x, v.y, h01, l01);
    split2(v.z, v.w, h23, l23);
    size_t o = (size_t)i * 4;
    *(__nv_bfloat162*)&hi[o]     = h01;
    *(__nv_bfloat162*)&hi[o + 2] = h23;
    *(__nv_bfloat162*)&lo[o]     = l01;
    *(__nv_bfloat162*)&lo[o + 2] = l23;
}

// ---------------------------------------------------------------------------
// LayerNorm -> bf16 hi/lo (one block per row of 1024)
// ---------------------------------------------------------------------------
__global__ void __launch_bounds__(256) ln_kernel(
    const float* __restrict__ x, const float* __restrict__ gg,
    const float* __restrict__ bb, __nv_bfloat16* __restrict__ hi,
    __nv_bfloat16* __restrict__ lo)
{
    int row = blockIdx.x;
    int tid = threadIdx.x;
    float4 v = ((const float4*)(x + (size_t)row * Dd))[tid];
    float s  = v.x + v.y + v.z + v.w;
    float ss = v.x*v.x + v.y*v.y + v.z*v.z + v.w*v.w;
    #pragma unroll
    for (int o = 16; o; o >>= 1) {
        s  += __shfl_down_sync(0xffffffffu, s,  o);
        ss += __shfl_down_sync(0xffffffffu, ss, o);
    }
    __shared__ float sh_s[8], sh_ss[8];
    __shared__ float sh_m, sh_r;
    int w = tid >> 5, lane = tid & 31;
    if (!lane) { sh_s[w] = s; sh_ss[w] = ss; }
    __syncthreads();
    if (tid == 0) {
        float S = 0.f, SS = 0.f;
        #pragma unroll
        for (int i = 0; i < 8; ++i) { S += sh_s[i]; SS += sh_ss[i]; }
        float m = S * (1.0f / Dd);
        sh_m = m;
        sh_r = rsqrtf(SS * (1.0f / Dd) - m * m + 1e-5f);
    }
    __syncthreads();
    float m = sh_m, r = sh_r;
    float4 g4 = ((const float4*)gg)[tid];
    float4 b4 = ((const float4*)bb)[tid];
    float ox = (v.x - m) * r * g4.x + b4.x;
    float oy = (v.y - m) * r * g4.y + b4.y;
    float oz = (v.z - m) * r * g4.z + b4.z;
    float ow = (v.w - m) * r * g4.w + b4.w;
    __nv_bfloat162 h01, l01, h23, l23;
    split2(ox, oy, h01, l01);
    split2(oz, ow, h23, l23);
    size_t o = (size_t)row * Dd + tid * 4;
    *(__nv_bfloat162*)&hi[o]     = h01;
    *(__nv_bfloat162*)&hi[o + 2] = h23;
    *(__nv_bfloat162*)&lo[o]     = l01;
    *(__nv_bfloat162*)&lo[o + 2] = l23;
}

// ---------------------------------------------------------------------------
// x1 = x + gate*h ; x2n = LN(x1) -> bf16 hi/lo.  One block per row.
// ---------------------------------------------------------------------------
__global__ void __launch_bounds__(256) combine_ln2_kernel(
    const float* __restrict__ x, const float* __restrict__ gate,
    const float* __restrict__ h, const float* __restrict__ g2,
    const float* __restrict__ b2, float* __restrict__ x1,
    __nv_bfloat16* __restrict__ hi, __nv_bfloat16* __restrict__ lo)
{
    int row = blockIdx.x;
    int tid = threadIdx.x;
    size_t off = (size_t)row * 256 + tid;
    float4 xv = ((const float4*)x)[off];
    float4 gv = ((const float4*)gate)[off];
    float4 hv = ((const float4*)h)[off];
    float4 v;
    v.x = xv.x + gv.x * hv.x;
    v.y = xv.y + gv.y * hv.y;
    v.z = xv.z + gv.z * hv.z;
    v.w = xv.w + gv.w * hv.w;
    ((float4*)x1)[off] = v;

    float s  = v.x + v.y + v.z + v.w;
    float ss = v.x*v.x + v.y*v.y + v.z*v.z + v.w*v.w;
    #pragma unroll
    for (int o = 16; o; o >>= 1) {
        s  += __shfl_down_sync(0xffffffffu, s,  o);
        ss += __shfl_down_sync(0xffffffffu, ss, o);
    }
    __shared__ float sh_s[8], sh_ss[8];
    __shared__ float sh_m, sh_r;
    int w = tid >> 5, lane = tid & 31;
    if (!lane) { sh_s[w] = s; sh_ss[w] = ss; }
    __syncthreads();
    if (tid == 0) {
        float S = 0.f, SS = 0.f;
        #pragma unroll
        for (int i = 0; i < 8; ++i) { S += sh_s[i]; SS += sh_ss[i]; }
        float m = S * (1.0f / Dd);
        sh_m = m;
        sh_r = rsqrtf(SS * (1.0f / Dd) - m * m + 1e-5f);
    }
    __syncthreads();
    float m = sh_m, r = sh_r;
    float4 g4 = ((const float4*)g2)[tid];
    float4 b4 = ((const float4*)b2)[tid];
    float ox = (v.x - m) * r * g4.x + b4.x;
    float oy = (v.y - m) * r * g4.y + b4.y;
    float oz = (v.z - m) * r * g4.z + b4.z;
    float ow = (v.w - m) * r * g4.w + b4.w;
    __nv_bfloat162 h01, l01, h23, l23;
    split2(ox, oy, h01, l01);
    split2(oz, ow, h23, l23);
    size_t o = off * 4;
    *(__nv_bfloat162*)&hi[o]     = h01;
    *(__nv_bfloat162*)&hi[o + 2] = h23;
    *(__nv_bfloat162*)&lo[o]     = l01;
    *(__nv_bfloat162*)&lo[o + 2] = l23;
}

// ---------------------------------------------------------------------------
// Phase A: intra-chunk BACKWARD complex scan, in place on g_beta (fp32).
// ---------------------------------------------------------------------------
__global__ void __launch_bounds__(256) phaseA_kernel(
    float* __restrict__ beta, const float* __restrict__ ld,
    const float* __restrict__ fr)
{
    int tid = blockIdx.x * 256 + threadIdx.x;
    int k = tid & 63;
    int chunk = (tid >> 6) & 63;
    int b = tid >> 12;
    float mag = 1.0f / (1.0f + expf(-ld[k]));
    float f = fr[k];
    float lr = mag * cosf(f), li = mag * sinf(f);
    size_t base = ((size_t)(b * Tt + chunk * Cc)) * 128 + k;
    float cr = 0.f, ci = 0.f;
    for (int j = Cc - 1; j >= 0; --j) {
        size_t idx = base + (size_t)j * 128;
        float br = beta[idx];
        float bi = beta[idx + 64];
        float nr = br + lr * cr - li * ci;
        float ni = bi + lr * ci + li * cr;
        cr = nr; ci = ni;
        beta[idx]      = cr;
        beta[idx + 64] = ci;
    }
}

// ---------------------------------------------------------------------------
// Phase C: carry + 16x16 coupling -> bf16 hi/lo.  One block per token.
// ---------------------------------------------------------------------------
__global__ void __launch_bounds__(128) phaseC_kernel(
    const float* __restrict__ intra, const float* __restrict__ coup,
    __nv_bfloat16* __restrict__ chi, __nv_bfloat16* __restrict__ clo)
{
    int tg = blockIdx.x;
    int t = tg & (Tt - 1);
    int tid = threadIdx.x;

    __shared__ float cs[128];
    __shared__ float coups[Hh * KHh * KHh];
    #pragma unroll
    for (int i = tid; i < Hh * KHh * KHh; i += 128) coups[i] = coup[i];

    if (tid < 64) {
        int k = tid;
        size_t ib = (size_t)tg * 128 + k;
        float ir = intra[ib];
        float ii = intra[ib + 64];
        if (((t & (Cc - 1)) == 0) && (t > 0)) {
            size_t pb = (size_t)(tg - 1) * 128 + k;
            ir += intra[pb];
            ii += intra[pb + 64];
        }
        cs[k]      = ir;
        cs[64 + k] = ii;
    }
    __syncthreads();

    int m = tid;
    int part = m >> 6;
    int mm = m & 63;
    int hh = mm >> 4, j = mm & 15;
    const float* cp = &coups[(hh * KHh + j) * KHh];
    const float* cv = &cs[part * 64 + hh * KHh];
    float acc = 0.f;
    #pragma unroll
    for (int k = 0; k < KHh; ++k) acc += cp[k] * cv[k];
    size_t o = (size_t)tg * 128 + m;
    __nv_bfloat16 h = __float2bfloat16_rn(acc);
    chi[o] = h;
    clo[o] = __float2bfloat16_rn(acc - __bfloat162float(h));
}

// ---------------------------------------------------------------------------
// Tensor-core GEMM, pre-split bf16 hi/lo inputs, cp.async double buffer.
//   C(MxN) = (Ahi+Alo)(MxKd) * (Whi+Wlo)(NxKd)^T, fp32 accumulate,
//   3 MMAs per product (hh + hl + lh).
// Tile 128x128x32, 256 threads (8 warps: 4(m) x 2(n)), warp tile 32x64.
// Dynamic smem: 2 stages x 4 arrays x 128x40 bf16 = 80 KB.
// EPI: 0 fp32 out; 1 sigmoid(z+b) fp32; 2 silu(z+b) -> bf16 hi/lo out;
//      3 z+b+res fp32
// ---------------------------------------------------------------------------
__device__ __forceinline__ void ldsm_x4(uint32_t* r, uint32_t addr) {
    asm volatile("ldmatrix.sync.aligned.m8n8.x4.shared.b16 {%0,%1,%2,%3}, [%4];"
                 : "=r"(r[0]), "=r"(r[1]), "=r"(r[2]), "=r"(r[3]) : "r"(addr));
}
__device__ __forceinline__ void mma_bf16(float* d, const uint32_t* a, const uint32_t* b) {
    asm volatile(
        "mma.sync.aligned.m16n8k16.row.col.f32.bf16.bf16.f32 "
        "{%0,%1,%2,%3}, {%4,%5,%6,%7}, {%8,%9}, {%0,%1,%2,%3};"
        : "+f"(d[0]), "+f"(d[1]), "+f"(d[2]), "+f"(d[3])
        : "r"(a[0]), "r"(a[1]), "r"(a[2]), "r"(a[3]), "r"(b[0]), "r"(b[1]));
}
__device__ __forceinline__ void cp16(uint32_t d, const void* s) {
    asm volatile("cp.async.cg.shared.global [%0], [%1], 16;" :: "r"(d), "l"(s));
}
__device__ __forceinline__ void cp_commit() {
    asm volatile("cp.async.commit_group;");
}
template <int Nn> __device__ __forceinline__ void cp_wait() {
    asm volatile("cp.async.wait_group %0;" :: "n"(Nn));
}

#define LDP 40                       // padded bf16 row stride
#define TSE (128 * LDP)              // elems per smem array
#define GEMM_SMEM (2 * 4 * TSE * 2)  // bytes (81920)

template <int EPI>
__global__ void __launch_bounds__(256) mma_gemm_bf16(
    const __nv_bfloat16* __restrict__ Ahi, const __nv_bfloat16* __restrict__ Alo,
    const __nv_bfloat16* __restrict__ Whi, const __nv_bfloat16* __restrict__ Wlo,
    const float* __restrict__ bias, const float* __restrict__ res,
    float* __restrict__ Cout, __nv_bfloat16* __restrict__ Ch,
    __nv_bfloat16* __restrict__ Cl, int M, int N, int Kd)
{
    extern __shared__ __nv_bfloat16 sm[];

    int t = threadIdx.x;
    int lane = t & 31, w = t >> 5;
    int wm = (w & 3) * 32;
    int wn = (w >> 2) * 64;
    int m0 = blockIdx.y * 128;
    int n0 = blockIdx.x * 128;

    int a_row = wm + (lane & 15);
    int a_coladd = (lane >> 4) << 3;
    int b_row = wn + (lane & 7) + ((lane >> 4) << 3);
    int b_coladd = ((lane >> 3) & 1) << 3;

    uint32_t sbase = (uint32_t)__cvta_generic_to_shared(sm);

    float acc[2][8][4];
    #pragma unroll
    for (int i = 0; i < 2; ++i)
        #pragma unroll
        for (int j = 0; j < 8; ++j)
            #pragma unroll
            for (int e = 0; e < 4; ++e) acc[i][j][e] = 0.f;

    int nk = Kd >> 5;

    auto issue_stage = [&](int s, int kt) {
        uint32_t stb = sbase + (uint32_t)s * (4u * TSE * 2u);
        int k0 = kt * 32;
        #pragma unroll
        for (int it = 0; it < 2; ++it) {
            int c = t + it * 256;          // 0..511
            int row = c >> 2;
            int off8 = (c & 3) * 8;        // 0,8,16,24 elems = 16B chunks
            uint32_t dsto = (uint32_t)(row * LDP + off8) * 2u;
            size_t asrc = (size_t)(m0 + row) * Kd + k0 + off8;
            size_t bsrc = (size_t)(n0 + row) * Kd + k0 + off8;
            cp16(stb + dsto,                Ahi + asrc);
            cp16(stb + (uint32_t)(TSE*2) + dsto,     Alo + asrc);
            cp16(stb + (uint32_t)(2*TSE*2) + dsto,   Whi + bsrc);
            cp16(stb + (uint32_t)(3*TSE*2) + dsto,   Wlo + bsrc);
        }
        cp_commit();
    };

    issue_stage(0, 0);

    for (int kt = 0; kt < nk; ++kt) {
        int s = kt & 1;
        if (kt + 1 < nk) {
            issue_stage(1 - s, kt + 1);
            cp_wait<1>();
        } else {
            cp_wait<0>();
        }
        __syncthreads();

        uint32_t stb = sbase + (uint32_t)s * (4u * TSE * 2u);
        #pragma unroll
        for (int kk = 0; kk < 32; kk += 16) {
            uint32_t Ah[2][4], Al[2][4], Bh[4][4], Bl[4][4];
            #pragma unroll
            for (int im = 0; im < 2; ++im) {
                uint32_t off = (uint32_t)((a_row + im * 16) * LDP + kk + a_coladd) * 2;
                ldsm_x4(Ah[im], stb + off);
                ldsm_x4(Al[im], stb + (uint32_t)(TSE*2) + off);
            }
            #pragma unroll
            for (int q = 0; q < 4; ++q) {
                uint32_t off = (uint32_t)((b_row + q * 16) * LDP + kk + b_coladd) * 2;
                ldsm_x4(Bh[q], stb + (uint32_t)(2*TSE*2) + off);
                ldsm_x4(Bl[q], stb + (uint32_t)(3*TSE*2) + off);
            }
            #pragma unroll
            for (int im = 0; im < 2; ++im)
                #pragma unroll
                for (int q = 0; q < 4; ++q)
                    #pragma unroll
                    for (int hf = 0; hf < 2; ++hf) {
                        float* d = acc[im][q * 2 + hf];
                        mma_bf16(d, Ah[im], &Bh[q][hf * 2]);
                        mma_bf16(d, Ah[im], &Bl[q][hf * 2]);
                        mma_bf16(d, Al[im], &Bh[q][hf * 2]);
                    }
        }
        __syncthreads();
    }

    // epilogue
    #pragma unroll
    for (int im = 0; im < 2; ++im) {
        int r0 = m0 + wm + im * 16 + (lane >> 2);
        #pragma unroll
        for (int jn = 0; jn < 8; ++jn) {
            int c0 = n0 + wn + jn * 8 + (lane & 3) * 2;
            float b0 = 0.f, b1 = 0.f;
            if (EPI != 0) { b0 = bias[c0]; b1 = bias[c0 + 1]; }
            float z[4] = {acc[im][jn][0], acc[im][jn][1],
                          acc[im][jn][2], acc[im][jn][3]};
            #pragma unroll
            for (int e = 0; e < 4; ++e) {
                float bb = (e & 1) ? b1 : b0;
                float v = z[e];
                if (EPI == 1) { v += bb; v = 1.0f / (1.0f + expf(-v)); }
                else if (EPI == 2) { v += bb; v = v / (1.0f + expf(-v)); }
                z[e] = v;
            }
            size_t o0 = (size_t)r0 * N + c0;
            size_t o1 = (size_t)(r0 + 8) * N + c0;
            if (EPI == 2) {
                __nv_bfloat162 h01, l01, h23, l23;
                split2(z[0], z[1], h01, l01);
                split2(z[2], z[3], h23, l23);
                *(__nv_bfloat162*)&Ch[o0] = h01;
                *(__nv_bfloat162*)&Cl[o0] = l01;
                *(__nv_bfloat162*)&Ch[o1] = h23;
                *(__nv_bfloat162*)&Cl[o1] = l23;
            } else {
                if (EPI == 3) {
                    z[0] += b0 + res[o0]; z[1] += b1 + res[o0 + 1];
                    z[2] += b0 + res[o1]; z[3] += b1 + res[o1 + 1];
                }
                *(float2*)&Cout[o0] = make_float2(z[0], z[1]);
                *(float2*)&Cout[o1] = make_float2(z[2], z[3]);
            }
        }
    }
}

// ---------------------------------------------------------------------------
// Launch
// ---------------------------------------------------------------------------
extern "C" void kernel_launch(void* const* d_in, const int* in_sizes, int n_in,
                              void* d_out, int out_size)
{
    const float* x         = (const float*)d_in[0];
    const float* w_in      = (const float*)d_in[1];
    const float* w_out     = (const float*)d_in[2];
    const float* w_gate    = (const float*)d_in[3];
    const float* b_gate    = (const float*)d_in[4];
    const float* log_decay = (const float*)d_in[5];
    const float* frequency = (const float*)d_in[6];
    const float* coupling  = (const float*)d_in[7];
    const float* w_mlp1    = (const float*)d_in[8];
    const float* b_mlp1    = (const float*)d_in[9];
    const float* w_mlp2    = (const float*)d_in[10];
    const float* b_mlp2    = (const float*)d_in[11];
    const float* ln1_g     = (const float*)d_in[12];
    const float* ln1_b     = (const float*)d_in[13];
    const float* ln2_g     = (const float*)d_in[14];
    const float* ln2_b     = (const float*)d_in[15];
    float* out = (float*)d_out;

    __nv_bfloat16 *xnh, *xnl, *chi, *clo, *x2h, *x2l, *hih, *hil;
    __nv_bfloat16 *winh, *winl, *wgth, *wgtl, *wouth, *woutl, *wm1h, *wm1l, *wm2h, *wm2l;
    float *beta, *gate, *hbuf, *x1;
    cudaGetSymbolAddress((void**)&xnh,  g_xn_hi);
    cudaGetSymbolAddress((void**)&xnl,  g_xn_lo);
    cudaGetSymbolAddress((void**)&beta, g_beta);
    cudaGetSymbolAddress((void**)&chi,  g_c_hi);
    cudaGetSymbolAddress((void**)&clo,  g_c_lo);
    cudaGetSymbolAddress((void**)&gate, g_gate);
    cudaGetSymbolAddress((void**)&hbuf, g_h);
    cudaGetSymbolAddress((void**)&x1,   g_x1);
    cudaGetSymbolAddress((void**)&x2h,  g_x2_hi);
    cudaGetSymbolAddress((void**)&x2l,  g_x2_lo);
    cudaGetSymbolAddress((void**)&hih,  g_hid_hi);
    cudaGetSymbolAddress((void**)&hil,  g_hid_lo);
    cudaGetSymbolAddress((void**)&winh,  g_win_hi);
    cudaGetSymbolAddress((void**)&winl,  g_win_lo);
    cudaGetSymbolAddress((void**)&wgth,  g_wgt_hi);
    cudaGetSymbolAddress((void**)&wgtl,  g_wgt_lo);
    cudaGetSymbolAddress((void**)&wouth, g_wout_hi);
    cudaGetSymbolAddress((void**)&woutl, g_wout_lo);
    cudaGetSymbolAddress((void**)&wm1h,  g_wm1_hi);
    cudaGetSymbolAddress((void**)&wm1l,  g_wm1_lo);
    cudaGetSymbolAddress((void**)&wm2h,  g_wm2_hi);
    cudaGetSymbolAddress((void**)&wm2l,  g_wm2_lo);

    // raise dynamic smem limit for the GEMM instantiations (idempotent)
    cudaFuncSetAttribute(mma_gemm_bf16<0>, cudaFuncAttributeMaxDynamicSharedMemorySize, GEMM_SMEM);
    cudaFuncSetAttribute(mma_gemm_bf16<1>, cudaFuncAttributeMaxDynamicSharedMemorySize, GEMM_SMEM);
    cudaFuncSetAttribute(mma_gemm_bf16<2>, cudaFuncAttributeMaxDynamicSharedMemorySize, GEMM_SMEM);
    cudaFuncSetAttribute(mma_gemm_bf16<3>, cudaFuncAttributeMaxDynamicSharedMemorySize, GEMM_SMEM);

    // 0. split weights (bandwidth-trivial pre-passes)
    split_kernel<<<(2*Kk*Dd/4 + 255)/256, 256>>>(w_in,   winh,  winl,  2*Kk*Dd/4);
    split_kernel<<<(Dd*Dd/4 + 255)/256, 256>>>(w_gate,  wgth,  wgtl,  Dd*Dd/4);
    split_kernel<<<(Dd*2*Kk/4 + 255)/256, 256>>>(w_out, wouth, woutl, Dd*2*Kk/4);
    split_kernel<<<(MLPd*Dd/4 + 255)/256, 256>>>(w_mlp1, wm1h, wm1l,  MLPd*Dd/4);
    split_kernel<<<(Dd*MLPd/4 + 255)/256, 256>>>(w_mlp2, wm2h, wm2l,  Dd*MLPd/4);

    // 1. LN1 -> xnorm hi/lo
    ln_kernel<<<Ntok, 256>>>(x, ln1_g, ln1_b, xnh, xnl);
    // 2. beta = xnorm @ w_in^T   (16384 x 128 x 1024), fp32 out
    mma_gemm_bf16<0><<<dim3(1, Ntok/128), 256, GEMM_SMEM>>>(
        xnh, xnl, winh, winl, nullptr, nullptr, beta, nullptr, nullptr,
        Ntok, 128, Dd);
    // 3. intra-chunk backward scan (in place, fp32)
    phaseA_kernel<<<64, 256>>>(beta, log_decay, frequency);
    // 4. carry + coupling -> c hi/lo
    phaseC_kernel<<<Ntok, 128>>>(beta, coupling, chi, clo);
    // 5. gate = sigmoid(xnorm @ w_gate^T + b_gate), fp32 out
    mma_gemm_bf16<1><<<dim3(Dd/128, Ntok/128), 256, GEMM_SMEM>>>(
        xnh, xnl, wgth, wgtl, b_gate, nullptr, gate, nullptr, nullptr,
        Ntok, Dd, Dd);
    // 6. h = c @ w_out^T   (16384 x 1024 x 128), fp32 out
    mma_gemm_bf16<0><<<dim3(Dd/128, Ntok/128), 256, GEMM_SMEM>>>(
        chi, clo, wouth, woutl, nullptr, nullptr, hbuf, nullptr, nullptr,
        Ntok, Dd, 2*Kk);
    // 7. x1 = x + gate*h ; x2n = LN2(x1) -> hi/lo
    combine_ln2_kernel<<<Ntok, 256>>>(x, gate, hbuf, ln2_g, ln2_b, x1, x2h, x2l);
    // 8. hid = silu(x2n @ w_mlp1^T + b1) -> bf16 hi/lo out
    mma_gemm_bf16<2><<<dim3(MLPd/128, Ntok/128), 256, GEMM_SMEM>>>(
        x2h, x2l, wm1h, wm1l, b_mlp1, nullptr, nullptr, hih, hil,
        Ntok, MLPd, Dd);
    // 9. out = hid @ w_mlp2^T + b2 + x1, fp32 out
    mma_gemm_bf16<3><<<dim3(Dd/128, Ntok/128), 256, GEMM_SMEM>>>(
        hih, hil, wm2h, wm2l, b_mlp2, x1, out, nullptr, nullptr,
        Ntok, Dd, MLPd);
    (void)in_sizes; (void)n_in; (void)out_size;
}

// round 11
// speedup vs baseline: 3.9832x; 1.3760x over previous
#include <cuda_runtime.h>
#include <cuda_fp16.h>
#include <cstdint>
#include <cmath>

// ---------------------------------------------------------------------------
// Problem constants
// ---------------------------------------------------------------------------
#define Bb 4
#define Tt 4096
#define Dd 1024
#define Kk 64
#define Hh 4
#define KHh 16
#define Cc 64
#define MLPd 4096
#define Ntok (Bb * Tt)          // 16384 tokens

// ---------------------------------------------------------------------------
// Scratch (static __device__ arrays; no allocation anywhere)
// A-side activations: fp16 hi/lo split.  B-side weights: single fp16.
// ---------------------------------------------------------------------------
__device__ __half g_xn_hi [(size_t)Ntok * Dd];
__device__ __half g_xn_lo [(size_t)Ntok * Dd];
__device__ float  g_beta  [(size_t)Ntok * 2 * Kk];
__device__ __half g_c_hi  [(size_t)Ntok * 2 * Kk];
__device__ __half g_c_lo  [(size_t)Ntok * 2 * Kk];
__device__ float  g_gate  [(size_t)Ntok * Dd];
__device__ float  g_h     [(size_t)Ntok * Dd];
__device__ float  g_x1    [(size_t)Ntok * Dd];
__device__ __half g_x2_hi [(size_t)Ntok * Dd];
__device__ __half g_x2_lo [(size_t)Ntok * Dd];
__device__ __half g_hid_hi[(size_t)Ntok * MLPd];
__device__ __half g_hid_lo[(size_t)Ntok * MLPd];
// fp16 weights (single precision copy)
__device__ __half g_win_h [2 * Kk * Dd];
__device__ __half g_wgt_h [Dd * Dd];
__device__ __half g_wout_h[Dd * 2 * Kk];
__device__ __half g_wm1_h [(size_t)MLPd * Dd];
__device__ __half g_wm2_h [(size_t)Dd * MLPd];

// ---------------------------------------------------------------------------
// helpers
// ---------------------------------------------------------------------------
__device__ __forceinline__ void split2h(float a, float b,
                                        __half2& h, __half2& l) {
    h = __floats2half2_rn(a, b);
    l = __floats2half2_rn(a - __low2float(h), b - __high2float(h));
}

// ---------------------------------------------------------------------------
// Weight convert: fp32 -> fp16 (single)
// ---------------------------------------------------------------------------
__global__ void __launch_bounds__(256) wconv_kernel(
    const float* __restrict__ in, __half* __restrict__ out, int n4)
{
    int i = blockIdx.x * 256 + threadIdx.x;
    if (i >= n4) return;
    float4 v = ((const float4*)in)[i];
    size_t o = (size_t)i * 4;
    *(__half2*)&out[o]     = __floats2half2_rn(v.x, v.y);
    *(__half2*)&out[o + 2] = __floats2half2_rn(v.z, v.w);
}

// ---------------------------------------------------------------------------
// LayerNorm -> fp16 hi/lo (one block per row of 1024)
// ---------------------------------------------------------------------------
__global__ void __launch_bounds__(256) ln_kernel(
    const float* __restrict__ x, const float* __restrict__ gg,
    const float* __restrict__ bb, __half* __restrict__ hi,
    __half* __restrict__ lo)
{
    int row = blockIdx.x;
    int tid = threadIdx.x;
    float4 v = ((const float4*)(x + (size_t)row * Dd))[tid];
    float s  = v.x + v.y + v.z + v.w;
    float ss = v.x*v.x + v.y*v.y + v.z*v.z + v.w*v.w;
    #pragma unroll
    for (int o = 16; o; o >>= 1) {
        s  += __shfl_down_sync(0xffffffffu, s,  o);
        ss += __shfl_down_sync(0xffffffffu, ss, o);
    }
    __shared__ float sh_s[8], sh_ss[8];
    __shared__ float sh_m, sh_r;
    int w = tid >> 5, lane = tid & 31;
    if (!lane) { sh_s[w] = s; sh_ss[w] = ss; }
    __syncthreads();
    if (tid == 0) {
        float S = 0.f, SS = 0.f;
        #pragma unroll
        for (int i = 0; i < 8; ++i) { S += sh_s[i]; SS += sh_ss[i]; }
        float m = S * (1.0f / Dd);
        sh_m = m;
        sh_r = rsqrtf(SS * (1.0f / Dd) - m * m + 1e-5f);
    }
    __syncthreads();
    float m = sh_m, r = sh_r;
    float4 g4 = ((const float4*)gg)[tid];
    float4 b4 = ((const float4*)bb)[tid];
    float ox = (v.x - m) * r * g4.x + b4.x;
    float oy = (v.y - m) * r * g4.y + b4.y;
    float oz = (v.z - m) * r * g4.z + b4.z;
    float ow = (v.w - m) * r * g4.w + b4.w;
    __half2 h01, l01, h23, l23;
    split2h(ox, oy, h01, l01);
    split2h(oz, ow, h23, l23);
    size_t o = (size_t)row * Dd + tid * 4;
    *(__half2*)&hi[o]     = h01;
    *(__half2*)&hi[o + 2] = h23;
    *(__half2*)&lo[o]     = l01;
    *(__half2*)&lo[o + 2] = l23;
}

// ---------------------------------------------------------------------------
// x1 = x + gate*h ; x2n = LN(x1) -> fp16 hi/lo.  One block per row.
// ---------------------------------------------------------------------------
__global__ void __launch_bounds__(256) combine_ln2_kernel(
    const float* __restrict__ x, const float* __restrict__ gate,
    const float* __restrict__ h, const float* __restrict__ g2,
    const float* __restrict__ b2, float* __restrict__ x1,
    __half* __restrict__ hi, __half* __restrict__ lo)
{
    int row = blockIdx.x;
    int tid = threadIdx.x;
    size_t off = (size_t)row * 256 + tid;
    float4 xv = ((const float4*)x)[off];
    float4 gv = ((const float4*)gate)[off];
    float4 hv = ((const float4*)h)[off];
    float4 v;
    v.x = xv.x + gv.x * hv.x;
    v.y = xv.y + gv.y * hv.y;
    v.z = xv.z + gv.z * hv.z;
    v.w = xv.w + gv.w * hv.w;
    ((float4*)x1)[off] = v;

    float s  = v.x + v.y + v.z + v.w;
    float ss = v.x*v.x + v.y*v.y + v.z*v.z + v.w*v.w;
    #pragma unroll
    for (int o = 16; o; o >>= 1) {
        s  += __shfl_down_sync(0xffffffffu, s,  o);
        ss += __shfl_down_sync(0xffffffffu, ss, o);
    }
    __shared__ float sh_s[8], sh_ss[8];
    __shared__ float sh_m, sh_r;
    int w = tid >> 5, lane = tid & 31;
    if (!lane) { sh_s[w] = s; sh_ss[w] = ss; }
    __syncthreads();
    if (tid == 0) {
        float S = 0.f, SS = 0.f;
        #pragma unroll
        for (int i = 0; i < 8; ++i) { S += sh_s[i]; SS += sh_ss[i]; }
        float m = S * (1.0f / Dd);
        sh_m = m;
        sh_r = rsqrtf(SS * (1.0f / Dd) - m * m + 1e-5f);
    }
    __syncthreads();
    float m = sh_m, r = sh_r;
    float4 g4 = ((const float4*)g2)[tid];
    float4 b4 = ((const float4*)b2)[tid];
    float ox = (v.x - m) * r * g4.x + b4.x;
    float oy = (v.y - m) * r * g4.y + b4.y;
    float oz = (v.z - m) * r * g4.z + b4.z;
    float ow = (v.w - m) * r * g4.w + b4.w;
    __half2 h01, l01, h23, l23;
    split2h(ox, oy, h01, l01);
    split2h(oz, ow, h23, l23);
    size_t o = off * 4;
    *(__half2*)&hi[o]     = h01;
    *(__half2*)&hi[o + 2] = h23;
    *(__half2*)&lo[o]     = l01;
    *(__half2*)&lo[o + 2] = l23;
}

// ---------------------------------------------------------------------------
// Phase A: intra-chunk BACKWARD complex scan, in place (fp32).
// ---------------------------------------------------------------------------
__global__ void __launch_bounds__(256) phaseA_kernel(
    float* __restrict__ beta, const float* __restrict__ ld,
    const float* __restrict__ fr)
{
    int tid = blockIdx.x * 256 + threadIdx.x;
    int k = tid & 63;
    int chunk = (tid >> 6) & 63;
    int b = tid >> 12;
    float mag = 1.0f / (1.0f + expf(-ld[k]));
    float f = fr[k];
    float lr = mag * cosf(f), li = mag * sinf(f);
    size_t base = ((size_t)(b * Tt + chunk * Cc)) * 128 + k;
    float cr = 0.f, ci = 0.f;
    for (int j = Cc - 1; j >= 0; --j) {
        size_t idx = base + (size_t)j * 128;
        float br = beta[idx];
        float bi = beta[idx + 64];
        float nr = br + lr * cr - li * ci;
        float ni = bi + lr * ci + li * cr;
        cr = nr; ci = ni;
        beta[idx]      = cr;
        beta[idx + 64] = ci;
    }
}

// ---------------------------------------------------------------------------
// Phase C: carry + 16x16 coupling -> fp16 hi/lo.  One block per token.
// ---------------------------------------------------------------------------
__global__ void __launch_bounds__(128) phaseC_kernel(
    const float* __restrict__ intra, const float* __restrict__ coup,
    __half* __restrict__ chi, __half* __restrict__ clo)
{
    int tg = blockIdx.x;
    int t = tg & (Tt - 1);
    int tid = threadIdx.x;

    __shared__ float cs[128];
    __shared__ float coups[Hh * KHh * KHh];
    #pragma unroll
    for (int i = tid; i < Hh * KHh * KHh; i += 128) coups[i] = coup[i];

    if (tid < 64) {
        int k = tid;
        size_t ib = (size_t)tg * 128 + k;
        float ir = intra[ib];
        float ii = intra[ib + 64];
        if (((t & (Cc - 1)) == 0) && (t > 0)) {
            size_t pb = (size_t)(tg - 1) * 128 + k;
            ir += intra[pb];
            ii += intra[pb + 64];
        }
        cs[k]      = ir;
        cs[64 + k] = ii;
    }
    __syncthreads();

    int m = tid;
    int part = m >> 6;
    int mm = m & 63;
    int hh = mm >> 4, j = mm & 15;
    const float* cp = &coups[(hh * KHh + j) * KHh];
    const float* cv = &cs[part * 64 + hh * KHh];
    float acc = 0.f;
    #pragma unroll
    for (int k = 0; k < KHh; ++k) acc += cp[k] * cv[k];
    size_t o = (size_t)tg * 128 + m;
    __half h = __float2half_rn(acc);
    chi[o] = h;
    clo[o] = __float2half_rn(acc - __half2float(h));
}

// ---------------------------------------------------------------------------
// Tensor-core GEMM, fp16, cp.async double buffer.
//   C(MxN) = (Ahi+Alo)(MxKd) * Wh(NxKd)^T, fp32 accumulate, 2 MMAs per
//   product (Ah*Bh + Al*Bh).  A hi/lo carries ~22 mantissa bits, so the
//   only error is the fp16 weight rounding (~2^-12 rel).
// Tile 128x128x32, 256 threads (8 warps: 4(m) x 2(n)), warp tile 32x64.
// Dynamic smem: 2 stages x 3 arrays x 128x40 fp16 = 60 KB.
// EPI: 0 fp32 out; 1 sigmoid(z+b); 2 silu(z+b) -> fp16 hi/lo out; 3 z+b+res
// ---------------------------------------------------------------------------
__device__ __forceinline__ void ldsm_x4(uint32_t* r, uint32_t addr) {
    asm volatile("ldmatrix.sync.aligned.m8n8.x4.shared.b16 {%0,%1,%2,%3}, [%4];"
                 : "=r"(r[0]), "=r"(r[1]), "=r"(r[2]), "=r"(r[3]) : "r"(addr));
}
__device__ __forceinline__ void mma_f16(float* d, const uint32_t* a, const uint32_t* b) {
    asm volatile(
        "mma.sync.aligned.m16n8k16.row.col.f32.f16.f16.f32 "
        "{%0,%1,%2,%3}, {%4,%5,%6,%7}, {%8,%9}, {%0,%1,%2,%3};"
        : "+f"(d[0]), "+f"(d[1]), "+f"(d[2]), "+f"(d[3])
        : "r"(a[0]), "r"(a[1]), "r"(a[2]), "r"(a[3]), "r"(b[0]), "r"(b[1]));
}
__device__ __forceinline__ void cp16(uint32_t d, const void* s) {
    asm volatile("cp.async.cg.shared.global [%0], [%1], 16;" :: "r"(d), "l"(s));
}
__device__ __forceinline__ void cp_commit() {
    asm volatile("cp.async.commit_group;");
}
template <int Nn> __device__ __forceinline__ void cp_wait() {
    asm volatile("cp.async.wait_group %0;" :: "n"(Nn));
}

#define LDP 40                       // padded fp16 row stride
#define TSE (128 * LDP)              // elems per smem array
#define GEMM_SMEM (2 * 3 * TSE * 2)  // bytes (61440)

template <int EPI>
__global__ void __launch_bounds__(256) mma_gemm_f16(
    const __half* __restrict__ Ahi, const __half* __restrict__ Alo,
    const __half* __restrict__ Wh,
    const float* __restrict__ bias, const float* __restrict__ res,
    float* __restrict__ Cout, __half* __restrict__ Ch,
    __half* __restrict__ Cl, int M, int N, int Kd)
{
    extern __shared__ __half sm[];

    int t = threadIdx.x;
    int lane = t & 31, w = t >> 5;
    int wm = (w & 3) * 32;
    int wn = (w >> 2) * 64;
    int m0 = blockIdx.y * 128;
    int n0 = blockIdx.x * 128;

    int a_row = wm + (lane & 15);
    int a_coladd = (lane >> 4) << 3;
    int b_row = wn + (lane & 7) + ((lane >> 4) << 3);
    int b_coladd = ((lane >> 3) & 1) << 3;

    uint32_t sbase = (uint32_t)__cvta_generic_to_shared(sm);

    float acc[2][8][4];
    #pragma unroll
    for (int i = 0; i < 2; ++i)
        #pragma unroll
        for (int j = 0; j < 8; ++j)
            #pragma unroll
            for (int e = 0; e < 4; ++e) acc[i][j][e] = 0.f;

    int nk = Kd >> 5;

    auto issue_stage = [&](int s, int kt) {
        uint32_t stb = sbase + (uint32_t)s * (3u * TSE * 2u);
        int k0 = kt * 32;
        #pragma unroll
        for (int it = 0; it < 2; ++it) {
            int c = t + it * 256;          // 0..511
            int row = c >> 2;
            int off8 = (c & 3) * 8;        // 0,8,16,24 elems = 16B chunks
            uint32_t dsto = (uint32_t)(row * LDP + off8) * 2u;
            size_t asrc = (size_t)(m0 + row) * Kd + k0 + off8;
            size_t bsrc = (size_t)(n0 + row) * Kd + k0 + off8;
            cp16(stb + dsto,                         Ahi + asrc);
            cp16(stb + (uint32_t)(TSE * 2) + dsto,   Alo + asrc);
            cp16(stb + (uint32_t)(2 * TSE * 2) + dsto, Wh + bsrc);
        }
        cp_commit();
    };

    issue_stage(0, 0);

    for (int kt = 0; kt < nk; ++kt) {
        int s = kt & 1;
        if (kt + 1 < nk) {
            issue_stage(1 - s, kt + 1);
            cp_wait<1>();
        } else {
            cp_wait<0>();
        }
        __syncthreads();

        uint32_t stb = sbase + (uint32_t)s * (3u * TSE * 2u);
        #pragma unroll
        for (int kk = 0; kk < 32; kk += 16) {
            uint32_t Ah[2][4], Al[2][4], Bh[4][4];
            #pragma unroll
            for (int im = 0; im < 2; ++im) {
                uint32_t off = (uint32_t)((a_row + im * 16) * LDP + kk + a_coladd) * 2;
                ldsm_x4(Ah[im], stb + off);
                ldsm_x4(Al[im], stb + (uint32_t)(TSE * 2) + off);
            }
            #pragma unroll
            for (int q = 0; q < 4; ++q) {
                uint32_t off = (uint32_t)((b_row + q * 16) * LDP + kk + b_coladd) * 2;
                ldsm_x4(Bh[q], stb + (uint32_t)(2 * TSE * 2) + off);
            }
            #pragma unroll
            for (int im = 0; im < 2; ++im)
                #pragma unroll
                for (int q = 0; q < 4; ++q)
                    #pragma unroll
                    for (int hf = 0; hf < 2; ++hf) {
                        float* d = acc[im][q * 2 + hf];
                        mma_f16(d, Ah[im], &Bh[q][hf * 2]);
                        mma_f16(d, Al[im], &Bh[q][hf * 2]);
                    }
        }
        __syncthreads();
    }

    // epilogue
    #pragma unroll
    for (int im = 0; im < 2; ++im) {
        int r0 = m0 + wm + im * 16 + (lane >> 2);
        #pragma unroll
        for (int jn = 0; jn < 8; ++jn) {
            int c0 = n0 + wn + jn * 8 + (lane & 3) * 2;
            float b0 = 0.f, b1 = 0.f;
            if (EPI != 0) { b0 = bias[c0]; b1 = bias[c0 + 1]; }
            float z[4] = {acc[im][jn][0], acc[im][jn][1],
                          acc[im][jn][2], acc[im][jn][3]};
            #pragma unroll
            for (int e = 0; e < 4; ++e) {
                float bb = (e & 1) ? b1 : b0;
                float v = z[e];
                if (EPI == 1) { v += bb; v = 1.0f / (1.0f + expf(-v)); }
                else if (EPI == 2) { v += bb; v = v / (1.0f + expf(-v)); }
                z[e] = v;
            }
            size_t o0 = (size_t)r0 * N + c0;
            size_t o1 = (size_t)(r0 + 8) * N + c0;
            if (EPI == 2) {
                __half2 h01, l01, h23, l23;
                split2h(z[0], z[1], h01, l01);
                split2h(z[2], z[3], h23, l23);
                *(__half2*)&Ch[o0] = h01;
                *(__half2*)&Cl[o0] = l01;
                *(__half2*)&Ch[o1] = h23;
                *(__half2*)&Cl[o1] = l23;
            } else {
                if (EPI == 3) {
                    z[0] += b0 + res[o0]; z[1] += b1 + res[o0 + 1];
                    z[2] += b0 + res[o1]; z[3] += b1 + res[o1 + 1];
                }
                *(float2*)&Cout[o0] = make_float2(z[0], z[1]);
                *(float2*)&Cout[o1] = make_float2(z[2], z[3]);
            }
        }
    }
}

// ---------------------------------------------------------------------------
// Launch
// ---------------------------------------------------------------------------
extern "C" void kernel_launch(void* const* d_in, const int* in_sizes, int n_in,
                              void* d_out, int out_size)
{
    const float* x         = (const float*)d_in[0];
    const float* w_in      = (const float*)d_in[1];
    const float* w_out     = (const float*)d_in[2];
    const float* w_gate    = (const float*)d_in[3];
    const float* b_gate    = (const float*)d_in[4];
    const float* log_decay = (const float*)d_in[5];
    const float* frequency = (const float*)d_in[6];
    const float* coupling  = (const float*)d_in[7];
    const float* w_mlp1    = (const float*)d_in[8];
    const float* b_mlp1    = (const float*)d_in[9];
    const float* w_mlp2    = (const float*)d_in[10];
    const float* b_mlp2    = (const float*)d_in[11];
    const float* ln1_g     = (const float*)d_in[12];
    const float* ln1_b     = (const float*)d_in[13];
    const float* ln2_g     = (const float*)d_in[14];
    const float* ln2_b     = (const float*)d_in[15];
    float* out = (float*)d_out;

    __half *xnh, *xnl, *chi, *clo, *x2h, *x2l, *hih, *hil;
    __half *winh, *wgth, *wouth, *wm1h, *wm2h;
    float *beta, *gate, *hbuf, *x1;
    cudaGetSymbolAddress((void**)&xnh,  g_xn_hi);
    cudaGetSymbolAddress((void**)&xnl,  g_xn_lo);
    cudaGetSymbolAddress((void**)&beta, g_beta);
    cudaGetSymbolAddress((void**)&chi,  g_c_hi);
    cudaGetSymbolAddress((void**)&clo,  g_c_lo);
    cudaGetSymbolAddress((void**)&gate, g_gate);
    cudaGetSymbolAddress((void**)&hbuf, g_h);
    cudaGetSymbolAddress((void**)&x1,   g_x1);
    cudaGetSymbolAddress((void**)&x2h,  g_x2_hi);
    cudaGetSymbolAddress((void**)&x2l,  g_x2_lo);
    cudaGetSymbolAddress((void**)&hih,  g_hid_hi);
    cudaGetSymbolAddress((void**)&hil,  g_hid_lo);
    cudaGetSymbolAddress((void**)&winh,  g_win_h);
    cudaGetSymbolAddress((void**)&wgth,  g_wgt_h);
    cudaGetSymbolAddress((void**)&wouth, g_wout_h);
    cudaGetSymbolAddress((void**)&wm1h,  g_wm1_h);
    cudaGetSymbolAddress((void**)&wm2h,  g_wm2_h);

    cudaFuncSetAttribute(mma_gemm_f16<0>, cudaFuncAttributeMaxDynamicSharedMemorySize, GEMM_SMEM);
    cudaFuncSetAttribute(mma_gemm_f16<1>, cudaFuncAttributeMaxDynamicSharedMemorySize, GEMM_SMEM);
    cudaFuncSetAttribute(mma_gemm_f16<2>, cudaFuncAttributeMaxDynamicSharedMemorySize, GEMM_SMEM);
    cudaFuncSetAttribute(mma_gemm_f16<3>, cudaFuncAttributeMaxDynamicSharedMemorySize, GEMM_SMEM);

    // 0. weights -> fp16
    wconv_kernel<<<(2*Kk*Dd/4 + 255)/256, 256>>>(w_in,   winh,  2*Kk*Dd/4);
    wconv_kernel<<<(Dd*Dd/4 + 255)/256, 256>>>(w_gate,  wgth,  Dd*Dd/4);
    wconv_kernel<<<(Dd*2*Kk/4 + 255)/256, 256>>>(w_out, wouth, Dd*2*Kk/4);
    wconv_kernel<<<(MLPd*Dd/4 + 255)/256, 256>>>(w_mlp1, wm1h, MLPd*Dd/4);
    wconv_kernel<<<(Dd*MLPd/4 + 255)/256, 256>>>(w_mlp2, wm2h, Dd*MLPd/4);

    // 1. LN1 -> xnorm hi/lo
    ln_kernel<<<Ntok, 256>>>(x, ln1_g, ln1_b, xnh, xnl);
    // 2. beta = xnorm @ w_in^T   (16384 x 128 x 1024), fp32 out
    mma_gemm_f16<0><<<dim3(1, Ntok/128), 256, GEMM_SMEM>>>(
        xnh, xnl, winh, nullptr, nullptr, beta, nullptr, nullptr,
        Ntok, 128, Dd);
    // 3. intra-chunk backward scan (in place, fp32)
    phaseA_kernel<<<64, 256>>>(beta, log_decay, frequency);
    // 4. carry + coupling -> c hi/lo
    phaseC_kernel<<<Ntok, 128>>>(beta, coupling, chi, clo);
    // 5. gate = sigmoid(xnorm @ w_gate^T + b_gate), fp32 out
    mma_gemm_f16<1><<<dim3(Dd/128, Ntok/128), 256, GEMM_SMEM>>>(
        xnh, xnl, wgth, b_gate, nullptr, gate, nullptr, nullptr,
        Ntok, Dd, Dd);
    // 6. h = c @ w_out^T   (16384 x 1024 x 128), fp32 out
    mma_gemm_f16<0><<<dim3(Dd/128, Ntok/128), 256, GEMM_SMEM>>>(
        chi, clo, wouth, nullptr, nullptr, hbuf, nullptr, nullptr,
        Ntok, Dd, 2*Kk);
    // 7. x1 = x + gate*h ; x2n = LN2(x1) -> hi/lo
    combine_ln2_kernel<<<Ntok, 256>>>(x, gate, hbuf, ln2_g, ln2_b, x1, x2h, x2l);
    // 8. hid = silu(x2n @ w_mlp1^T + b1) -> fp16 hi/lo out
    mma_gemm_f16<2><<<dim3(MLPd/128, Ntok/128), 256, GEMM_SMEM>>>(
        x2h, x2l, wm1h, b_mlp1, nullptr, nullptr, hih, hil,
        Ntok, MLPd, Dd);
    // 9. out = hid @ w_mlp2^T + b2 + x1, fp32 out
    mma_gemm_f16<3><<<dim3(Dd/128, Ntok/128), 256, GEMM_SMEM>>>(
        hih, hil, wm2h, b_mlp2, x1, out, nullptr, nullptr,
        Ntok, Dd, MLPd);
    (void)in_sizes; (void)n_in; (void)out_size;
}

// round 12
// speedup vs baseline: 6.2473x; 1.5684x over previous
#include <cuda_runtime.h>
#include <cuda_fp16.h>
#include <cstdint>
#include <cmath>

// ---------------------------------------------------------------------------
// Problem constants
// ---------------------------------------------------------------------------
#define Bb 4
#define Tt 4096
#define Dd 1024
#define Kk 64
#define Hh 4
#define KHh 16
#define Cc 64
#define MLPd 4096
#define Ntok (Bb * Tt)          // 16384 tokens

// ---------------------------------------------------------------------------
// Scratch (static __device__ arrays; no allocation anywhere)
// Single fp16 for all GEMM operands (activations + weights).
// ---------------------------------------------------------------------------
__device__ __half g_xn  [(size_t)Ntok * Dd];
__device__ float  g_beta[(size_t)Ntok * 2 * Kk];
__device__ __half g_c   [(size_t)Ntok * 2 * Kk];
__device__ float  g_gate[(size_t)Ntok * Dd];
__device__ float  g_h   [(size_t)Ntok * Dd];
__device__ float  g_x1  [(size_t)Ntok * Dd];
__device__ __half g_x2  [(size_t)Ntok * Dd];
__device__ __half g_hid [(size_t)Ntok * MLPd];
// fp16 weights
__device__ __half g_win_h [2 * Kk * Dd];
__device__ __half g_wgt_h [Dd * Dd];
__device__ __half g_wout_h[Dd * 2 * Kk];
__device__ __half g_wm1_h [(size_t)MLPd * Dd];
__device__ __half g_wm2_h [(size_t)Dd * MLPd];

// ---------------------------------------------------------------------------
// Weight convert: fp32 -> fp16
// ---------------------------------------------------------------------------
__global__ void __launch_bounds__(256) wconv_kernel(
    const float* __restrict__ in, __half* __restrict__ out, int n4)
{
    int i = blockIdx.x * 256 + threadIdx.x;
    if (i >= n4) return;
    float4 v = ((const float4*)in)[i];
    size_t o = (size_t)i * 4;
    *(__half2*)&out[o]     = __floats2half2_rn(v.x, v.y);
    *(__half2*)&out[o + 2] = __floats2half2_rn(v.z, v.w);
}

// ---------------------------------------------------------------------------
// LayerNorm -> fp16 (one block per row of 1024)
// ---------------------------------------------------------------------------
__global__ void __launch_bounds__(256) ln_kernel(
    const float* __restrict__ x, const float* __restrict__ gg,
    const float* __restrict__ bb, __half* __restrict__ outh)
{
    int row = blockIdx.x;
    int tid = threadIdx.x;
    float4 v = ((const float4*)(x + (size_t)row * Dd))[tid];
    float s  = v.x + v.y + v.z + v.w;
    float ss = v.x*v.x + v.y*v.y + v.z*v.z + v.w*v.w;
    #pragma unroll
    for (int o = 16; o; o >>= 1) {
        s  += __shfl_down_sync(0xffffffffu, s,  o);
        ss += __shfl_down_sync(0xffffffffu, ss, o);
    }
    __shared__ float sh_s[8], sh_ss[8];
    __shared__ float sh_m, sh_r;
    int w = tid >> 5, lane = tid & 31;
    if (!lane) { sh_s[w] = s; sh_ss[w] = ss; }
    __syncthreads();
    if (tid == 0) {
        float S = 0.f, SS = 0.f;
        #pragma unroll
        for (int i = 0; i < 8; ++i) { S += sh_s[i]; SS += sh_ss[i]; }
        float m = S * (1.0f / Dd);
        sh_m = m;
        sh_r = rsqrtf(SS * (1.0f / Dd) - m * m + 1e-5f);
    }
    __syncthreads();
    float m = sh_m, r = sh_r;
    float4 g4 = ((const float4*)gg)[tid];
    float4 b4 = ((const float4*)bb)[tid];
    float ox = (v.x - m) * r * g4.x + b4.x;
    float oy = (v.y - m) * r * g4.y + b4.y;
    float oz = (v.z - m) * r * g4.z + b4.z;
    float ow = (v.w - m) * r * g4.w + b4.w;
    size_t o = (size_t)row * Dd + tid * 4;
    *(__half2*)&outh[o]     = __floats2half2_rn(ox, oy);
    *(__half2*)&outh[o + 2] = __floats2half2_rn(oz, ow);
}

// ---------------------------------------------------------------------------
// x1 = x + gate*h ; x2n = LN(x1) -> fp16.  One block per row.
// ---------------------------------------------------------------------------
__global__ void __launch_bounds__(256) combine_ln2_kernel(
    const float* __restrict__ x, const float* __restrict__ gate,
    const float* __restrict__ h, const float* __restrict__ g2,
    const float* __restrict__ b2, float* __restrict__ x1,
    __half* __restrict__ outh)
{
    int row = blockIdx.x;
    int tid = threadIdx.x;
    size_t off = (size_t)row * 256 + tid;
    float4 xv = ((const float4*)x)[off];
    float4 gv = ((const float4*)gate)[off];
    float4 hv = ((const float4*)h)[off];
    float4 v;
    v.x = xv.x + gv.x * hv.x;
    v.y = xv.y + gv.y * hv.y;
    v.z = xv.z + gv.z * hv.z;
    v.w = xv.w + gv.w * hv.w;
    ((float4*)x1)[off] = v;

    float s  = v.x + v.y + v.z + v.w;
    float ss = v.x*v.x + v.y*v.y + v.z*v.z + v.w*v.w;
    #pragma unroll
    for (int o = 16; o; o >>= 1) {
        s  += __shfl_down_sync(0xffffffffu, s,  o);
        ss += __shfl_down_sync(0xffffffffu, ss, o);
    }
    __shared__ float sh_s[8], sh_ss[8];
    __shared__ float sh_m, sh_r;
    int w = tid >> 5, lane = tid & 31;
    if (!lane) { sh_s[w] = s; sh_ss[w] = ss; }
    __syncthreads();
    if (tid == 0) {
        float S = 0.f, SS = 0.f;
        #pragma unroll
        for (int i = 0; i < 8; ++i) { S += sh_s[i]; SS += sh_ss[i]; }
        float m = S * (1.0f / Dd);
        sh_m = m;
        sh_r = rsqrtf(SS * (1.0f / Dd) - m * m + 1e-5f);
    }
    __syncthreads();
    float m = sh_m, r = sh_r;
    float4 g4 = ((const float4*)g2)[tid];
    float4 b4 = ((const float4*)b2)[tid];
    float ox = (v.x - m) * r * g4.x + b4.x;
    float oy = (v.y - m) * r * g4.y + b4.y;
    float oz = (v.z - m) * r * g4.z + b4.z;
    float ow = (v.w - m) * r * g4.w + b4.w;
    size_t o = off * 4;
    *(__half2*)&outh[o]     = __floats2half2_rn(ox, oy);
    *(__half2*)&outh[o + 2] = __floats2half2_rn(oz, ow);
}

// ---------------------------------------------------------------------------
// Phase A: intra-chunk BACKWARD complex scan, in place (fp32).
// ---------------------------------------------------------------------------
__global__ void __launch_bounds__(256) phaseA_kernel(
    float* __restrict__ beta, const float* __restrict__ ld,
    const float* __restrict__ fr)
{
    int tid = blockIdx.x * 256 + threadIdx.x;
    int k = tid & 63;
    int chunk = (tid >> 6) & 63;
    int b = tid >> 12;
    float mag = 1.0f / (1.0f + expf(-ld[k]));
    float f = fr[k];
    float lr = mag * cosf(f), li = mag * sinf(f);
    size_t base = ((size_t)(b * Tt + chunk * Cc)) * 128 + k;
    float cr = 0.f, ci = 0.f;
    for (int j = Cc - 1; j >= 0; --j) {
        size_t idx = base + (size_t)j * 128;
        float br = beta[idx];
        float bi = beta[idx + 64];
        float nr = br + lr * cr - li * ci;
        float ni = bi + lr * ci + li * cr;
        cr = nr; ci = ni;
        beta[idx]      = cr;
        beta[idx + 64] = ci;
    }
}

// ---------------------------------------------------------------------------
// Phase C: carry + 16x16 coupling -> fp16.  One block per token.
// ---------------------------------------------------------------------------
__global__ void __launch_bounds__(128) phaseC_kernel(
    const float* __restrict__ intra, const float* __restrict__ coup,
    __half* __restrict__ cout)
{
    int tg = blockIdx.x;
    int t = tg & (Tt - 1);
    int tid = threadIdx.x;

    __shared__ float cs[128];
    __shared__ float coups[Hh * KHh * KHh];
    #pragma unroll
    for (int i = tid; i < Hh * KHh * KHh; i += 128) coups[i] = coup[i];

    if (tid < 64) {
        int k = tid;
        size_t ib = (size_t)tg * 128 + k;
        float ir = intra[ib];
        float ii = intra[ib + 64];
        if (((t & (Cc - 1)) == 0) && (t > 0)) {
            size_t pb = (size_t)(tg - 1) * 128 + k;
            ir += intra[pb];
            ii += intra[pb + 64];
        }
        cs[k]      = ir;
        cs[64 + k] = ii;
    }
    __syncthreads();

    int m = tid;
    int part = m >> 6;
    int mm = m & 63;
    int hh = mm >> 4, j = mm & 15;
    const float* cp = &coups[(hh * KHh + j) * KHh];
    const float* cv = &cs[part * 64 + hh * KHh];
    float acc = 0.f;
    #pragma unroll
    for (int k = 0; k < KHh; ++k) acc += cp[k] * cv[k];
    cout[(size_t)tg * 128 + m] = __float2half_rn(acc);
}

// ---------------------------------------------------------------------------
// Tensor-core GEMM, single fp16, 1 MMA per product, cp.async double buffer.
//   C(MxN) = A(MxKd) * W(NxKd)^T, fp32 accumulate.
// Tile 128x128x32, 256 threads (8 warps: 4(m) x 2(n)), warp tile 32x64.
// Dynamic smem: 2 stages x 2 arrays x 128x40 fp16 = 40 KB.
// EPI: 0 fp32 out; 1 sigmoid(z+b); 2 silu(z+b) -> fp16 out; 3 z+b+res
// ---------------------------------------------------------------------------
__device__ __forceinline__ void ldsm_x4(uint32_t* r, uint32_t addr) {
    asm volatile("ldmatrix.sync.aligned.m8n8.x4.shared.b16 {%0,%1,%2,%3}, [%4];"
                 : "=r"(r[0]), "=r"(r[1]), "=r"(r[2]), "=r"(r[3]) : "r"(addr));
}
__device__ __forceinline__ void mma_f16(float* d, const uint32_t* a, const uint32_t* b) {
    asm volatile(
        "mma.sync.aligned.m16n8k16.row.col.f32.f16.f16.f32 "
        "{%0,%1,%2,%3}, {%4,%5,%6,%7}, {%8,%9}, {%0,%1,%2,%3};"
        : "+f"(d[0]), "+f"(d[1]), "+f"(d[2]), "+f"(d[3])
        : "r"(a[0]), "r"(a[1]), "r"(a[2]), "r"(a[3]), "r"(b[0]), "r"(b[1]));
}
__device__ __forceinline__ void cp16(uint32_t d, const void* s) {
    asm volatile("cp.async.cg.shared.global [%0], [%1], 16;" :: "r"(d), "l"(s));
}
__device__ __forceinline__ void cp_commit() {
    asm volatile("cp.async.commit_group;");
}
template <int Nn> __device__ __forceinline__ void cp_wait() {
    asm volatile("cp.async.wait_group %0;" :: "n"(Nn));
}

#define LDP 40                       // padded fp16 row stride
#define TSE (128 * LDP)              // elems per smem array
#define GEMM_SMEM (2 * 2 * TSE * 2)  // bytes (40960)

template <int EPI>
__global__ void __launch_bounds__(256) mma_gemm_1h(
    const __half* __restrict__ A, const __half* __restrict__ Wh,
    const float* __restrict__ bias, const float* __restrict__ res,
    float* __restrict__ Cout, __half* __restrict__ Ch,
    int M, int N, int Kd)
{
    extern __shared__ __half sm[];

    int t = threadIdx.x;
    int lane = t & 31, w = t >> 5;
    int wm = (w & 3) * 32;
    int wn = (w >> 2) * 64;
    int m0 = blockIdx.y * 128;
    int n0 = blockIdx.x * 128;

    int a_row = wm + (lane & 15);
    int a_coladd = (lane >> 4) << 3;
    int b_row = wn + (lane & 7) + ((lane >> 4) << 3);
    int b_coladd = ((lane >> 3) & 1) << 3;

    uint32_t sbase = (uint32_t)__cvta_generic_to_shared(sm);

    float acc[2][8][4];
    #pragma unroll
    for (int i = 0; i < 2; ++i)
        #pragma unroll
        for (int j = 0; j < 8; ++j)
            #pragma unroll
            for (int e = 0; e < 4; ++e) acc[i][j][e] = 0.f;

    int nk = Kd >> 5;

    auto issue_stage = [&](int s, int kt) {
        uint32_t stb = sbase + (uint32_t)s * (2u * TSE * 2u);
        int k0 = kt * 32;
        #pragma unroll
        for (int it = 0; it < 2; ++it) {
            int c = t + it * 256;          // 0..511
            int row = c >> 2;
            int off8 = (c & 3) * 8;        // 0,8,16,24 elems = 16B chunks
            uint32_t dsto = (uint32_t)(row * LDP + off8) * 2u;
            size_t asrc = (size_t)(m0 + row) * Kd + k0 + off8;
            size_t bsrc = (size_t)(n0 + row) * Kd + k0 + off8;
            cp16(stb + dsto,                       A  + asrc);
            cp16(stb + (uint32_t)(TSE * 2) + dsto, Wh + bsrc);
        }
        cp_commit();
    };

    issue_stage(0, 0);

    for (int kt = 0; kt < nk; ++kt) {
        int s = kt & 1;
        if (kt + 1 < nk) {
            issue_stage(1 - s, kt + 1);
            cp_wait<1>();
        } else {
            cp_wait<0>();
        }
        __syncthreads();

        uint32_t stb = sbase + (uint32_t)s * (2u * TSE * 2u);
        #pragma unroll
        for (int kk = 0; kk < 32; kk += 16) {
            uint32_t Af[2][4], Bf[4][4];
            #pragma unroll
            for (int im = 0; im < 2; ++im) {
                uint32_t off = (uint32_t)((a_row + im * 16) * LDP + kk + a_coladd) * 2;
                ldsm_x4(Af[im], stb + off);
            }
            #pragma unroll
            for (int q = 0; q < 4; ++q) {
                uint32_t off = (uint32_t)((b_row + q * 16) * LDP + kk + b_coladd) * 2;
                ldsm_x4(Bf[q], stb + (uint32_t)(TSE * 2) + off);
            }
            #pragma unroll
            for (int im = 0; im < 2; ++im)
                #pragma unroll
                for (int q = 0; q < 4; ++q)
                    #pragma unroll
                    for (int hf = 0; hf < 2; ++hf)
                        mma_f16(acc[im][q * 2 + hf], Af[im], &Bf[q][hf * 2]);
        }
        __syncthreads();
    }

    // epilogue
    #pragma unroll
    for (int im = 0; im < 2; ++im) {
        int r0 = m0 + wm + im * 16 + (lane >> 2);
        #pragma unroll
        for (int jn = 0; jn < 8; ++jn) {
            int c0 = n0 + wn + jn * 8 + (lane & 3) * 2;
            float b0 = 0.f, b1 = 0.f;
            if (EPI != 0) { b0 = bias[c0]; b1 = bias[c0 + 1]; }
            float z[4] = {acc[im][jn][0], acc[im][jn][1],
                          acc[im][jn][2], acc[im][jn][3]};
            #pragma unroll
            for (int e = 0; e < 4; ++e) {
                float bb = (e & 1) ? b1 : b0;
                float v = z[e];
                if (EPI == 1) { v += bb; v = 1.0f / (1.0f + expf(-v)); }
                else if (EPI == 2) { v += bb; v = v / (1.0f + expf(-v)); }
                z[e] = v;
            }
            size_t o0 = (size_t)r0 * N + c0;
            size_t o1 = (size_t)(r0 + 8) * N + c0;
            if (EPI == 2) {
                *(__half2*)&Ch[o0] = __floats2half2_rn(z[0], z[1]);
                *(__half2*)&Ch[o1] = __floats2half2_rn(z[2], z[3]);
            } else {
                if (EPI == 3) {
                    z[0] += b0 + res[o0]; z[1] += b1 + res[o0 + 1];
                    z[2] += b0 + res[o1]; z[3] += b1 + res[o1 + 1];
                }
                *(float2*)&Cout[o0] = make_float2(z[0], z[1]);
                *(float2*)&Cout[o1] = make_float2(z[2], z[3]);
            }
        }
    }
}

// ---------------------------------------------------------------------------
// Launch
// ---------------------------------------------------------------------------
extern "C" void kernel_launch(void* const* d_in, const int* in_sizes, int n_in,
                              void* d_out, int out_size)
{
    const float* x         = (const float*)d_in[0];
    const float* w_in      = (const float*)d_in[1];
    const float* w_out     = (const float*)d_in[2];
    const float* w_gate    = (const float*)d_in[3];
    const float* b_gate    = (const float*)d_in[4];
    const float* log_decay = (const float*)d_in[5];
    const float* frequency = (const float*)d_in[6];
    const float* coupling  = (const float*)d_in[7];
    const float* w_mlp1    = (const float*)d_in[8];
    const float* b_mlp1    = (const float*)d_in[9];
    const float* w_mlp2    = (const float*)d_in[10];
    const float* b_mlp2    = (const float*)d_in[11];
    const float* ln1_g     = (const float*)d_in[12];
    const float* ln1_b     = (const float*)d_in[13];
    const float* ln2_g     = (const float*)d_in[14];
    const float* ln2_b     = (const float*)d_in[15];
    float* out = (float*)d_out;

    __half *xn, *cb, *x2, *hid;
    __half *winh, *wgth, *wouth, *wm1h, *wm2h;
    float *beta, *gate, *hbuf, *x1;
    cudaGetSymbolAddress((void**)&xn,   g_xn);
    cudaGetSymbolAddress((void**)&beta, g_beta);
    cudaGetSymbolAddress((void**)&cb,   g_c);
    cudaGetSymbolAddress((void**)&gate, g_gate);
    cudaGetSymbolAddress((void**)&hbuf, g_h);
    cudaGetSymbolAddress((void**)&x1,   g_x1);
    cudaGetSymbolAddress((void**)&x2,   g_x2);
    cudaGetSymbolAddress((void**)&hid,  g_hid);
    cudaGetSymbolAddress((void**)&winh,  g_win_h);
    cudaGetSymbolAddress((void**)&wgth,  g_wgt_h);
    cudaGetSymbolAddress((void**)&wouth, g_wout_h);
    cudaGetSymbolAddress((void**)&wm1h,  g_wm1_h);
    cudaGetSymbolAddress((void**)&wm2h,  g_wm2_h);

    cudaFuncSetAttribute(mma_gemm_1h<0>, cudaFuncAttributeMaxDynamicSharedMemorySize, GEMM_SMEM);
    cudaFuncSetAttribute(mma_gemm_1h<1>, cudaFuncAttributeMaxDynamicSharedMemorySize, GEMM_SMEM);
    cudaFuncSetAttribute(mma_gemm_1h<2>, cudaFuncAttributeMaxDynamicSharedMemorySize, GEMM_SMEM);
    cudaFuncSetAttribute(mma_gemm_1h<3>, cudaFuncAttributeMaxDynamicSharedMemorySize, GEMM_SMEM);

    // 0. weights -> fp16
    wconv_kernel<<<(2*Kk*Dd/4 + 255)/256, 256>>>(w_in,   winh,  2*Kk*Dd/4);
    wconv_kernel<<<(Dd*Dd/4 + 255)/256, 256>>>(w_gate,  wgth,  Dd*Dd/4);
    wconv_kernel<<<(Dd*2*Kk/4 + 255)/256, 256>>>(w_out, wouth, Dd*2*Kk/4);
    wconv_kernel<<<(MLPd*Dd/4 + 255)/256, 256>>>(w_mlp1, wm1h, MLPd*Dd/4);
    wconv_kernel<<<(Dd*MLPd/4 + 255)/256, 256>>>(w_mlp2, wm2h, Dd*MLPd/4);

    // 1. LN1 -> xnorm fp16
    ln_kernel<<<Ntok, 256>>>(x, ln1_g, ln1_b, xn);
    // 2. beta = xnorm @ w_in^T   (16384 x 128 x 1024), fp32 out
    mma_gemm_1h<0><<<dim3(1, Ntok/128), 256, GEMM_SMEM>>>(
        xn, winh, nullptr, nullptr, beta, nullptr, Ntok, 128, Dd);
    // 3. intra-chunk backward scan (in place, fp32)
    phaseA_kernel<<<64, 256>>>(beta, log_decay, frequency);
    // 4. carry + coupling -> c fp16
    phaseC_kernel<<<Ntok, 128>>>(beta, coupling, cb);
    // 5. gate = sigmoid(xnorm @ w_gate^T + b_gate), fp32 out
    mma_gemm_1h<1><<<dim3(Dd/128, Ntok/128), 256, GEMM_SMEM>>>(
        xn, wgth, b_gate, nullptr, gate, nullptr, Ntok, Dd, Dd);
    // 6. h = c @ w_out^T   (16384 x 1024 x 128), fp32 out
    mma_gemm_1h<0><<<dim3(Dd/128, Ntok/128), 256, GEMM_SMEM>>>(
        cb, wouth, nullptr, nullptr, hbuf, nullptr, Ntok, Dd, 2*Kk);
    // 7. x1 = x + gate*h ; x2n = LN2(x1) -> fp16
    combine_ln2_kernel<<<Ntok, 256>>>(x, gate, hbuf, ln2_g, ln2_b, x1, x2);
    // 8. hid = silu(x2n @ w_mlp1^T + b1) -> fp16 out
    mma_gemm_1h<2><<<dim3(MLPd/128, Ntok/128), 256, GEMM_SMEM>>>(
        x2, wm1h, b_mlp1, nullptr, nullptr, hid, Ntok, MLPd, Dd);
    // 9. out = hid @ w_mlp2^T + b2 + x1, fp32 out
    mma_gemm_1h<3><<<dim3(Dd/128, Ntok/128), 256, GEMM_SMEM>>>(
        hid, wm2h, b_mlp2, x1, out, nullptr, Ntok, Dd, MLPd);
    (void)in_sizes; (void)n_in; (void)out_size;
}